// round 1
// baseline (speedup 1.0000x reference)
#include <cuda_runtime.h>
#include <cstdint>
#include <cstddef>

// Problem dims
#define NB 8
#define C 128
#define HH 36
#define WW 36
#define P (HH*WW)          // 1296 query tokens
#define HV 34
#define WV 34
#define D (HV*WV)          // 1156 key/value tokens
#define KC (C*9)           // 1152 im2col K

// -------- scratch (static device memory; no allocation APIs) --------
__device__ float g_xa[(size_t)NB*2*C*P];     // rows 0..127: x, rows 128..255: a0
__device__ float g_col_s[(size_t)NB*KC*P];   // im2col SAME of x
__device__ float g_col_v[(size_t)NB*KC*D];   // im2col VALID of x
__device__ float g_q[(size_t)NB*C*P];
__device__ float g_k[(size_t)NB*C*D];
__device__ float g_v[(size_t)NB*C*D];
__device__ float g_sc[(size_t)NB*P*D];       // scores -> probs in place
__device__ float g_h[(size_t)NB*C*P];
__device__ float g_beff[C];

// -------- generic tiled SGEMM: C[M,N] = op(A)[M,K] @ op(B)[K,N] --------
// TA: A physically [K,M] (use columns). TB: B physically [N,K].
// EPI: 0 none, 1 +bias[m], 2 tanh(acc + bias[m])
#define BM 64
#define BN 64
#define BK 16

template<bool TA, bool TB, int EPI>
__global__ void __launch_bounds__(256) gemm_k(
    const float* __restrict__ A, size_t sA, int lda,
    const float* __restrict__ B, size_t sB, int ldb,
    float* __restrict__ Cp, size_t sC, int ldc,
    int M, int N, int K, const float* __restrict__ bias)
{
    __shared__ float As[BK][BM + 4];
    __shared__ float Bs[BK][BN + 4];
    A += (size_t)blockIdx.z * sA;
    B += (size_t)blockIdx.z * sB;
    Cp += (size_t)blockIdx.z * sC;
    const int m0 = blockIdx.y * BM, n0 = blockIdx.x * BN;
    const int tid = threadIdx.x;
    const int tx = tid & 15, ty = tid >> 4;

    float acc[4][4] = {};

    for (int k0 = 0; k0 < K; k0 += BK) {
        // ---- load A tile into As[k][m] ----
        #pragma unroll
        for (int i = 0; i < 4; i++) {
            int idx = tid + i * 256;
            if (!TA) {
                int k = idx % BK, m = idx / BK;
                int gm = m0 + m, gk = k0 + k;
                As[k][m] = (gm < M && gk < K) ? A[(size_t)gm * lda + gk] : 0.f;
            } else {
                int m = idx % BM, k = idx / BM;
                int gm = m0 + m, gk = k0 + k;
                As[k][m] = (gm < M && gk < K) ? A[(size_t)gk * lda + gm] : 0.f;
            }
        }
        // ---- load B tile into Bs[k][n] ----
        #pragma unroll
        for (int i = 0; i < 4; i++) {
            int idx = tid + i * 256;
            if (!TB) {
                int nn = idx % BN, k = idx / BN;
                int gn = n0 + nn, gk = k0 + k;
                Bs[k][nn] = (gn < N && gk < K) ? B[(size_t)gk * ldb + gn] : 0.f;
            } else {
                int k = idx % BK, nn = idx / BK;
                int gn = n0 + nn, gk = k0 + k;
                Bs[k][nn] = (gn < N && gk < K) ? B[(size_t)gn * ldb + gk] : 0.f;
            }
        }
        __syncthreads();
        #pragma unroll
        for (int kk = 0; kk < BK; kk++) {
            float a[4], b[4];
            #pragma unroll
            for (int i = 0; i < 4; i++) a[i] = As[kk][ty * 4 + i];
            #pragma unroll
            for (int j = 0; j < 4; j++) b[j] = Bs[kk][tx * 4 + j];
            #pragma unroll
            for (int i = 0; i < 4; i++)
                #pragma unroll
                for (int j = 0; j < 4; j++) acc[i][j] += a[i] * b[j];
        }
        __syncthreads();
    }

    #pragma unroll
    for (int i = 0; i < 4; i++) {
        int gm = m0 + ty * 4 + i;
        if (gm >= M) continue;
        float bv = (EPI >= 1) ? bias[gm] : 0.f;
        #pragma unroll
        for (int j = 0; j < 4; j++) {
            int gn = n0 + tx * 4 + j;
            if (gn >= N) continue;
            float val = acc[i][j] + bv;
            if (EPI == 2) val = tanhf(val);
            Cp[(size_t)gm * ldc + gn] = val;
        }
    }
}

// -------- im2col (SAME and VALID) of x stored in g_xa top half --------
__global__ void im2col_same_k(const float* __restrict__ xa, float* __restrict__ col)
{
    int n = blockIdx.z;
    int idx = blockIdx.x * blockDim.x + threadIdx.x;
    if (idx >= KC * P) return;
    int p = idx % P, k = idx / P;
    int ci = k / 9, t = k % 9, ky = t / 3, kx = t % 3;
    int y = p / WW, x = p % WW;
    int sy = y + ky - 1, sx = x + kx - 1;
    float v = 0.f;
    if (sy >= 0 && sy < HH && sx >= 0 && sx < WW)
        v = xa[((size_t)n * (2*C) + ci) * P + sy * WW + sx];
    col[((size_t)n * KC + k) * P + p] = v;
}

__global__ void im2col_valid_k(const float* __restrict__ xa, float* __restrict__ col)
{
    int n = blockIdx.z;
    int idx = blockIdx.x * blockDim.x + threadIdx.x;
    if (idx >= KC * D) return;
    int p = idx % D, k = idx / D;
    int ci = k / 9, t = k % 9, ky = t / 3, kx = t % 3;
    int y = p / WV, x = p % WV;
    int sy = y + ky, sx = x + kx;
    float v = xa[((size_t)n * (2*C) + ci) * P + sy * WW + sx];
    col[((size_t)n * KC + k) * D + p] = v;
}

// -------- row softmax over D for scores[n][q][:] --------
__global__ void softmax_k(float* __restrict__ sc)
{
    int n = blockIdx.z, qr = blockIdx.x;
    float* row = sc + ((size_t)n * P + qr) * D;
    __shared__ float red[256];
    int tid = threadIdx.x;
    float m = -1e30f;
    for (int d = tid; d < D; d += 256) m = fmaxf(m, row[d]);
    red[tid] = m; __syncthreads();
    for (int s = 128; s > 0; s >>= 1) { if (tid < s) red[tid] = fmaxf(red[tid], red[tid + s]); __syncthreads(); }
    m = red[0]; __syncthreads();
    float sum = 0.f;
    for (int d = tid; d < D; d += 256) { float e = __expf(row[d] - m); row[d] = e; sum += e; }
    red[tid] = sum; __syncthreads();
    for (int s = 128; s > 0; s >>= 1) { if (tid < s) red[tid] += red[tid + s]; __syncthreads(); }
    float inv = 1.0f / red[0];
    for (int d = tid; d < D; d += 256) row[d] *= inv;
}

// -------- beff = b_h + W_h[:,2C:3C] @ v_c, with v_c[c] = (sum_t w_vc[c,ci,t]) @ c0 --------
__global__ void beff_k(const float* __restrict__ w_vc, const float* __restrict__ c0,
                       const float* __restrict__ w_h, const float* __restrict__ b_h,
                       float* __restrict__ beff)
{
    __shared__ float vc[C];
    int c = threadIdx.x;  // 128 threads
    float s = 0.f;
    for (int ci = 0; ci < C; ci++) {
        float ws = 0.f;
        #pragma unroll
        for (int t = 0; t < 9; t++) ws += w_vc[((size_t)c * C + ci) * 9 + t];
        s += ws * c0[ci];
    }
    vc[c] = s;
    __syncthreads();
    float r = b_h[c];
    for (int j = 0; j < C; j++) r += w_h[(size_t)c * (3*C) + 2*C + j] * vc[j];
    beff[c] = r;
}

extern "C" void kernel_launch(void* const* d_in, const int* in_sizes, int n_in,
                              void* d_out, int out_size)
{
    const float* inp  = (const float*)d_in[0];
    const float* c0   = (const float*)d_in[1];
    const float* w_x  = (const float*)d_in[2];
    const float* b_x  = (const float*)d_in[3];
    const float* w_qx = (const float*)d_in[4];
    const float* w_kx = (const float*)d_in[6];
    const float* w_vx = (const float*)d_in[8];
    const float* w_vc = (const float*)d_in[9];
    const float* w_h  = (const float*)d_in[14];
    const float* b_h  = (const float*)d_in[15];
    const float* w_o  = (const float*)d_in[16];
    const float* b_o  = (const float*)d_in[17];
    float* out = (float*)d_out;

    float *xa, *col_s, *col_v, *q, *k, *v, *sc, *h, *beff;
    cudaGetSymbolAddress((void**)&xa,    g_xa);
    cudaGetSymbolAddress((void**)&col_s, g_col_s);
    cudaGetSymbolAddress((void**)&col_v, g_col_v);
    cudaGetSymbolAddress((void**)&q,     g_q);
    cudaGetSymbolAddress((void**)&k,     g_k);
    cudaGetSymbolAddress((void**)&v,     g_v);
    cudaGetSymbolAddress((void**)&sc,    g_sc);
    cudaGetSymbolAddress((void**)&h,     g_h);
    cudaGetSymbolAddress((void**)&beff,  g_beff);

    const int NT_P = (P + BN - 1) / BN;   // 21
    const int NT_D = (D + BN - 1) / BN;   // 19
    const int MT_P = (P + BM - 1) / BM;   // 21
    const int MT_C = (C + BM - 1) / BM;   // 2

    // folded constant bias for proj_h (v_c branch)
    beff_k<<<1, C>>>(w_vc, c0, w_h, b_h, beff);

    // x = W_x @ inp + b_x  -> g_xa rows [0,128)
    gemm_k<false,false,1><<<dim3(NT_P, MT_C, NB), 256>>>(
        w_x, 0, C, inp, (size_t)C*P, P, xa, (size_t)2*C*P, P, C, P, C, b_x);

    // im2col of x
    im2col_same_k<<<dim3((KC*P + 255)/256, 1, NB), 256>>>(xa, col_s);
    im2col_valid_k<<<dim3((KC*D + 255)/256, 1, NB), 256>>>(xa, col_v);

    // q/k/v 3x3 convs as GEMMs
    gemm_k<false,false,0><<<dim3(NT_P, MT_C, NB), 256>>>(
        w_qx, 0, KC, col_s, (size_t)KC*P, P, q, (size_t)C*P, P, C, P, KC, nullptr);
    gemm_k<false,false,0><<<dim3(NT_D, MT_C, NB), 256>>>(
        w_kx, 0, KC, col_v, (size_t)KC*D, D, k, (size_t)C*D, D, C, D, KC, nullptr);
    gemm_k<false,false,0><<<dim3(NT_D, MT_C, NB), 256>>>(
        w_vx, 0, KC, col_v, (size_t)KC*D, D, v, (size_t)C*D, D, C, D, KC, nullptr);

    // scores[q,d] = q^T k  (TN)
    gemm_k<true,false,0><<<dim3(NT_D, MT_P, NB), 256>>>(
        q, (size_t)C*P, P, k, (size_t)C*D, D, sc, (size_t)P*D, D, P, D, C, nullptr);

    // softmax rows
    softmax_k<<<dim3(P, 1, NB), 256>>>(sc);

    // a0 = v @ probs^T  (NT) -> g_xa rows [128,256)
    gemm_k<false,true,0><<<dim3(NT_P, MT_C, NB), 256>>>(
        v, (size_t)C*D, D, sc, (size_t)P*D, D, xa + (size_t)C*P, (size_t)2*C*P, P,
        C, P, D, nullptr);

    // h = tanh(W_h[:, :2C] @ [x; a0] + beff)
    gemm_k<false,false,2><<<dim3(NT_P, MT_C, NB), 256>>>(
        w_h, 0, 3*C, xa, (size_t)2*C*P, P, h, (size_t)C*P, P, C, P, 2*C, beff);

    // out = W_o @ h + b_o
    gemm_k<false,false,1><<<dim3(NT_P, MT_C, NB), 256>>>(
        w_o, 0, C, h, (size_t)C*P, P, out, (size_t)C*P, P, C, P, C, b_o);
}

// round 5
// speedup vs baseline: 1.1525x; 1.1525x over previous
#include <cuda_runtime.h>
#include <cstdint>
#include <cstddef>

// Problem dims
#define NB 8
#define C 128
#define HH 36
#define WW 36
#define P (HH*WW)          // 1296 query tokens
#define HV 34
#define WV 34
#define D (HV*WV)          // 1156 key/value tokens
#define KC (C*9)           // 1152 im2col K

// -------- scratch (static device memory; no allocation APIs) --------
__device__ float g_xa[(size_t)NB*2*C*P];     // rows 0..127: x, rows 128..255: a0
__device__ float g_q[(size_t)NB*C*P];
__device__ float g_k[(size_t)NB*C*D];
__device__ float g_v[(size_t)NB*C*D];
__device__ float g_sc[(size_t)NB*(size_t)P*D]; // scores -> probs in place
__device__ float g_h[(size_t)NB*C*P];
__device__ float g_beff[C];

// ============================================================
// gemm64: C[128,N] = A[128,K] @ B[K,N], 64x64 tile, 128 threads,
// 8x4 per-thread microtile. A now has a per-batch stride sA
// (0 for shared weights, C*D for per-batch v).
// BMODE: 0 = B plain [K][N] (ldb), 1 = B transposed [N][K] (ldb),
//        2 = B im2col-SAME from x [C][36][36], 3 = im2col-VALID
// EPI: 0 none, 1 +bias[m], 2 tanh(acc+bias[m])
// ============================================================
template<int BMODE, int EPI>
__global__ void __launch_bounds__(128) gemm64_k(
    const float* __restrict__ A, size_t sA, int lda,
    const float* __restrict__ B, size_t sB, int ldb,
    float* __restrict__ Cp, size_t sC, int ldc,
    int N, int K,
    const float* __restrict__ bias)
{
    __shared__ float As[16][68];
    __shared__ float Bs[16][68];
    A  += (size_t)blockIdx.z * sA;      // <-- the R2-R4 bug fix
    B  += (size_t)blockIdx.z * sB;
    Cp += (size_t)blockIdx.z * sC;

    const int m0 = blockIdx.y * 64, n0 = blockIdx.x * 64;
    const int tid = threadIdx.x;
    const int tx = tid & 15, ty = tid >> 4;

    float acc[8][4];
    #pragma unroll
    for (int i = 0; i < 8; i++)
        #pragma unroll
        for (int j = 0; j < 4; j++) acc[i][j] = 0.f;

    for (int k0 = 0; k0 < K; k0 += 16) {
        // ---- A tile: As[k][m] = A[m0+m][k0+k] ----
        #pragma unroll
        for (int i = 0; i < 8; i++) {
            int idx = tid + i * 128;
            int k = idx & 15, m = idx >> 4;
            int gk = k0 + k;
            As[k][m] = (gk < K) ? A[(size_t)(m0 + m) * lda + gk] : 0.f;
        }
        // ---- B tile: Bs[k][n] ----
        if (BMODE == 0) {
            #pragma unroll
            for (int i = 0; i < 8; i++) {
                int idx = tid + i * 128;
                int n = idx & 63, k = idx >> 6;
                int gn = n0 + n, gk = k0 + k;
                Bs[k][n] = (gn < N && gk < K) ? B[(size_t)gk * ldb + gn] : 0.f;
            }
        } else if (BMODE == 1) {
            #pragma unroll
            for (int i = 0; i < 8; i++) {
                int idx = tid + i * 128;
                int k = idx & 15, n = idx >> 4;
                int gn = n0 + n, gk = k0 + k;
                Bs[k][n] = (gn < N && gk < K) ? B[(size_t)gn * ldb + gk] : 0.f;
            }
        } else {
            #pragma unroll
            for (int i = 0; i < 8; i++) {
                int idx = tid + i * 128;
                int n = idx & 63, kr = idx >> 6;
                int kg = k0 + kr;
                int ci = kg / 9, t = kg % 9;
                int ky = t / 3, kx = t % 3;
                int p = n0 + n;
                float v = 0.f;
                if (BMODE == 2) {
                    if (p < P) {
                        int y = p / WW, x = p % WW;
                        int sy = y + ky - 1, sx = x + kx - 1;
                        if (sy >= 0 && sy < HH && sx >= 0 && sx < WW)
                            v = B[(size_t)ci * P + sy * WW + sx];
                    }
                } else {
                    if (p < D) {
                        int y = p / WV, x = p % WV;
                        v = B[(size_t)ci * P + (y + ky) * WW + (x + kx)];
                    }
                }
                Bs[kr][n] = v;
            }
        }
        __syncthreads();

        #pragma unroll
        for (int kk = 0; kk < 16; kk++) {
            float a[8], b[4];
            #pragma unroll
            for (int i = 0; i < 8; i++) a[i] = As[kk][ty * 8 + i];
            #pragma unroll
            for (int j = 0; j < 4; j++) b[j] = Bs[kk][tx * 4 + j];
            #pragma unroll
            for (int i = 0; i < 8; i++)
                #pragma unroll
                for (int j = 0; j < 4; j++) acc[i][j] += a[i] * b[j];
        }
        __syncthreads();
    }

    #pragma unroll
    for (int i = 0; i < 8; i++) {
        int gm = m0 + ty * 8 + i;
        float bv = (EPI >= 1) ? bias[gm] : 0.f;
        #pragma unroll
        for (int j = 0; j < 4; j++) {
            int gn = n0 + tx * 4 + j;
            if (gn < N) {
                float v2 = acc[i][j];
                if (EPI == 1) v2 += bv;
                if (EPI == 2) v2 = tanhf(v2 + bv);
                Cp[(size_t)gm * ldc + gn] = v2;
            }
        }
    }
}

// ============================================================
// gemm_big: scores[p][d] = sum_c q[c][p] * k[c][d]
// 128x128 tile, BK=8, 256 threads, 8x8 microtile, single-buffered.
// ============================================================
__global__ void __launch_bounds__(256) gemm_big_k(
    const float* __restrict__ Aq,   // [C][P] per batch
    const float* __restrict__ Bk,   // [C][D] per batch
    float* __restrict__ Cs)         // [P][D] per batch
{
    __shared__ float As[8][132];
    __shared__ float Bs[8][132];
    const float* Ab = Aq + (size_t)blockIdx.z * C * P;
    const float* Bb = Bk + (size_t)blockIdx.z * C * D;
    float* Cb = Cs + (size_t)blockIdx.z * (size_t)P * D;

    const int m0 = blockIdx.y * 128, n0 = blockIdx.x * 128;
    const int tid = threadIdx.x;
    const int kf = tid >> 5, e4 = (tid & 31) * 4;
    const int tx = tid & 15, ty = tid >> 4;

    float acc[8][8];
    #pragma unroll
    for (int i = 0; i < 8; i++)
        #pragma unroll
        for (int j = 0; j < 8; j++) acc[i][j] = 0.f;

    for (int k0 = 0; k0 < C; k0 += 8) {
        {
            const float* srcA = Ab + (size_t)(k0 + kf) * P;
            int m = m0 + e4;
            float4 ra;
            if (m + 3 < P) ra = *(const float4*)(srcA + m);
            else {
                ra.x = (m+0 < P) ? srcA[m+0] : 0.f;
                ra.y = (m+1 < P) ? srcA[m+1] : 0.f;
                ra.z = (m+2 < P) ? srcA[m+2] : 0.f;
                ra.w = (m+3 < P) ? srcA[m+3] : 0.f;
            }
            As[kf][e4+0] = ra.x; As[kf][e4+1] = ra.y;
            As[kf][e4+2] = ra.z; As[kf][e4+3] = ra.w;

            const float* srcB = Bb + (size_t)(k0 + kf) * D;
            int n = n0 + e4;
            float4 rb;
            if (n + 3 < D) rb = *(const float4*)(srcB + n);
            else {
                rb.x = (n+0 < D) ? srcB[n+0] : 0.f;
                rb.y = (n+1 < D) ? srcB[n+1] : 0.f;
                rb.z = (n+2 < D) ? srcB[n+2] : 0.f;
                rb.w = (n+3 < D) ? srcB[n+3] : 0.f;
            }
            Bs[kf][e4+0] = rb.x; Bs[kf][e4+1] = rb.y;
            Bs[kf][e4+2] = rb.z; Bs[kf][e4+3] = rb.w;
        }
        __syncthreads();

        #pragma unroll
        for (int kk = 0; kk < 8; kk++) {
            float a[8], b[8];
            #pragma unroll
            for (int r = 0; r < 4; r++) {
                a[r]     = As[kk][ty * 4 + r];
                a[r + 4] = As[kk][64 + ty * 4 + r];
                b[r]     = Bs[kk][tx * 4 + r];
                b[r + 4] = Bs[kk][64 + tx * 4 + r];
            }
            #pragma unroll
            for (int i = 0; i < 8; i++)
                #pragma unroll
                for (int j = 0; j < 8; j++) acc[i][j] += a[i] * b[j];
        }
        __syncthreads();
    }

    #pragma unroll
    for (int i = 0; i < 8; i++) {
        int gm = m0 + ((i < 4) ? (ty*4 + i) : (64 + ty*4 + i - 4));
        if (gm >= P) continue;
        #pragma unroll
        for (int j = 0; j < 8; j++) {
            int gn = n0 + ((j < 4) ? (tx*4 + j) : (64 + tx*4 + j - 4));
            if (gn < D)
                Cb[(size_t)gm * D + gn] = acc[i][j];
        }
    }
}

// -------- row softmax over D (R1-proven; normalizes in place) --------
__global__ void softmax_k(float* __restrict__ sc)
{
    int n = blockIdx.z, qr = blockIdx.x;
    float* row = sc + ((size_t)n * P + qr) * D;
    __shared__ float red[256];
    int tid = threadIdx.x;
    float m = -1e30f;
    for (int d = tid; d < D; d += 256) m = fmaxf(m, row[d]);
    red[tid] = m; __syncthreads();
    for (int s = 128; s > 0; s >>= 1) { if (tid < s) red[tid] = fmaxf(red[tid], red[tid + s]); __syncthreads(); }
    m = red[0]; __syncthreads();
    float sum = 0.f;
    for (int d = tid; d < D; d += 256) { float e = __expf(row[d] - m); row[d] = e; sum += e; }
    red[tid] = sum; __syncthreads();
    for (int s = 128; s > 0; s >>= 1) { if (tid < s) red[tid] += red[tid + s]; __syncthreads(); }
    float inv = 1.0f / red[0];
    for (int d = tid; d < D; d += 256) row[d] *= inv;
}

// -------- beff = b_h + W_h[:,2C:3C] @ v_c; v_c from constant c0 --------
__global__ void beff_k(const float* __restrict__ w_vc, const float* __restrict__ c0,
                       const float* __restrict__ w_h, const float* __restrict__ b_h,
                       float* __restrict__ beff)
{
    __shared__ float vc[C];
    int c = threadIdx.x;  // 128 threads
    float s = 0.f;
    for (int ci = 0; ci < C; ci++) {
        float ws = 0.f;
        #pragma unroll
        for (int t = 0; t < 9; t++) ws += w_vc[((size_t)c * C + ci) * 9 + t];
        s += ws * c0[ci];
    }
    vc[c] = s;
    __syncthreads();
    float r = b_h[c];
    for (int j = 0; j < C; j++) r += w_h[(size_t)c * (3*C) + 2*C + j] * vc[j];
    beff[c] = r;
}

extern "C" void kernel_launch(void* const* d_in, const int* in_sizes, int n_in,
                              void* d_out, int out_size)
{
    const float* inp  = (const float*)d_in[0];
    const float* c0   = (const float*)d_in[1];
    const float* w_x  = (const float*)d_in[2];
    const float* b_x  = (const float*)d_in[3];
    const float* w_qx = (const float*)d_in[4];
    const float* w_kx = (const float*)d_in[6];
    const float* w_vx = (const float*)d_in[8];
    const float* w_vc = (const float*)d_in[9];
    const float* w_h  = (const float*)d_in[14];
    const float* b_h  = (const float*)d_in[15];
    const float* w_o  = (const float*)d_in[16];
    const float* b_o  = (const float*)d_in[17];
    float* out = (float*)d_out;

    float *xa, *q, *k, *v, *sc, *h, *beff;
    cudaGetSymbolAddress((void**)&xa,   g_xa);
    cudaGetSymbolAddress((void**)&q,    g_q);
    cudaGetSymbolAddress((void**)&k,    g_k);
    cudaGetSymbolAddress((void**)&v,    g_v);
    cudaGetSymbolAddress((void**)&sc,   g_sc);
    cudaGetSymbolAddress((void**)&h,    g_h);
    cudaGetSymbolAddress((void**)&beff, g_beff);

    const int NT_P = (P + 63) / 64;   // 21
    const int NT_D = (D + 63) / 64;   // 19

    // folded constant bias for proj_h (v_c branch)
    beff_k<<<1, C>>>(w_vc, c0, w_h, b_h, beff);

    // x = W_x @ inp + b_x  -> g_xa rows [0,128)
    gemm64_k<0,1><<<dim3(NT_P, 2, NB), 128>>>(
        w_x, 0, C, inp, (size_t)C*P, P, xa, (size_t)2*C*P, P, P, C, b_x);

    // q/k/v 3x3 convs with fused im2col (A = shared weights, sA = 0)
    gemm64_k<2,0><<<dim3(NT_P, 2, NB), 128>>>(
        w_qx, 0, KC, xa, (size_t)2*C*P, 0, q, (size_t)C*P, P, P, KC, b_x);
    gemm64_k<3,0><<<dim3(NT_D, 2, NB), 128>>>(
        w_kx, 0, KC, xa, (size_t)2*C*P, 0, k, (size_t)C*D, D, D, KC, b_x);
    gemm64_k<3,0><<<dim3(NT_D, 2, NB), 128>>>(
        w_vx, 0, KC, xa, (size_t)2*C*P, 0, v, (size_t)C*D, D, D, KC, b_x);

    // scores[p,d] = q^T k
    gemm_big_k<<<dim3((D + 127)/128, (P + 127)/128, NB), 256>>>(q, k, sc);

    // softmax rows (normalize in place)
    softmax_k<<<dim3(P, 1, NB), 256>>>(sc);

    // a0[c,p] = v @ probs^T  -> g_xa rows [128,256)   (A = per-batch v, sA = C*D!)
    gemm64_k<1,0><<<dim3(NT_P, 2, NB), 128>>>(
        v, (size_t)C*D, D, sc, (size_t)P*D, D, xa + (size_t)C*P, (size_t)2*C*P, P, P, D, b_x);

    // h = tanh(W_h[:, :2C] @ [x; a0] + beff)
    gemm64_k<0,2><<<dim3(NT_P, 2, NB), 128>>>(
        w_h, 0, 3*C, xa, (size_t)2*C*P, P, h, (size_t)C*P, P, P, 2*C, beff);

    // out = W_o @ h + b_o
    gemm64_k<0,1><<<dim3(NT_P, 2, NB), 128>>>(
        w_o, 0, C, h, (size_t)C*P, P, out, (size_t)C*P, P, P, C, b_o);
}

// round 6
// speedup vs baseline: 1.6614x; 1.4416x over previous
#include <cuda_runtime.h>
#include <cstdint>
#include <cstddef>

// Problem dims
#define NB 8
#define C 128
#define HH 36
#define WW 36
#define P (HH*WW)          // 1296 query tokens
#define HV 34
#define WV 34
#define D (HV*WV)          // 1156 key/value tokens
#define KC (C*9)           // 1152 im2col K

// -------- scratch (static device memory; no allocation APIs) --------
__device__ float g_xa[(size_t)NB*2*C*P];     // rows 0..127: x, rows 128..255: a0
__device__ float g_q[(size_t)NB*C*P];
__device__ float g_k[(size_t)NB*C*D];
__device__ float g_v[(size_t)NB*C*D];
__device__ float g_sc[(size_t)NB*(size_t)P*D]; // scores -> probs in place
__device__ float g_h[(size_t)NB*C*P];
__device__ float g_beff[C];

// ============================================================
// gemm64: C[128,N] = A[128,K] @ B[K,N], 64x64 tile, 128 threads,
// 8x4 per-thread microtile. DOUBLE-BUFFERED (1 sync per chunk).
// BMODE: 0 = B plain [K][N] (ldb), 1 = B transposed [N][K] (ldb),
//        2 = B im2col-SAME from x [C][36][36], 3 = im2col-VALID
// For BMODE>=2 the K axis is reordered t-major: kg = t*128 + ci,
// and A is the weight read at A[m*KC + ci*9 + t] (same math, new order).
// EPI: 0 none, 1 +bias[m], 2 tanh(acc+bias[m])
// ============================================================
template<int BMODE, int EPI>
__global__ void __launch_bounds__(128) gemm64_k(
    const float* __restrict__ A, size_t sA, int lda,
    const float* __restrict__ B, size_t sB, int ldb,
    float* __restrict__ Cp, size_t sC, int ldc,
    int N, int K,
    const float* __restrict__ bias)
{
    __shared__ float As[2][16][68];
    __shared__ float Bs[2][16][68];
    A  += (size_t)blockIdx.z * sA;
    B  += (size_t)blockIdx.z * sB;
    Cp += (size_t)blockIdx.z * sC;

    const int m0 = blockIdx.y * 64, n0 = blockIdx.x * 64;
    const int tid = threadIdx.x;
    const int tx = tid & 15, ty = tid >> 4;

    // fixed per-thread slot coordinates
    const int ka = tid & 15;        // A: k within chunk (fixed), m = (tid>>4)+8i
    const int ma = tid >> 4;
    const int nb64 = tid & 63;      // BMODE 0/2/3: n fixed, k = (tid>>6)+2i
    const int kb2 = tid >> 6;
    const int kb16 = tid & 15;      // BMODE 1: k fixed, n = (tid>>4)+8i

    // im2col precompute (BMODE>=2): spatial coords of this thread's column
    int iy = 0, ix = 0; bool npred = true;
    if (BMODE >= 2) {
        int p = n0 + nb64;
        if (BMODE == 2) { npred = (p < P); if (p >= P) p = 0; iy = p / WW; ix = p % WW; }
        else            { npred = (p < D); if (p >= D) p = 0; iy = p / WV; ix = p % WV; }
    }

    float acc[8][4];
    #pragma unroll
    for (int i = 0; i < 8; i++)
        #pragma unroll
        for (int j = 0; j < 4; j++) acc[i][j] = 0.f;

    float ra[8], rb[8];

    // ---- register loaders ----
    auto loadAB = [&](int k0) {
        // A
        #pragma unroll
        for (int i = 0; i < 8; i++) {
            int gk = k0 + ka;
            int m = m0 + ma + 8 * i;
            if (BMODE >= 2) {
                int ci = gk & 127, t = gk >> 7;
                ra[i] = A[(size_t)m * KC + ci * 9 + t];
            } else {
                ra[i] = (gk < K) ? A[(size_t)m * lda + gk] : 0.f;
            }
        }
        // B
        if (BMODE == 0) {
            #pragma unroll
            for (int i = 0; i < 8; i++) {
                int gk = k0 + kb2 + 2 * i;
                int gn = n0 + nb64;
                rb[i] = (gn < N && gk < K) ? B[(size_t)gk * ldb + gn] : 0.f;
            }
        } else if (BMODE == 1) {
            #pragma unroll
            for (int i = 0; i < 8; i++) {
                int gn = n0 + (tid >> 4) + 8 * i;
                int gk = k0 + kb16;
                rb[i] = (gn < N && gk < K) ? B[(size_t)gn * ldb + gk] : 0.f;
            }
        } else {
            int t = k0 >> 7;            // constant within chunk
            int ky = t / 3, kx = t - ky * 3;
            int cb = k0 & 127;          // ci = cb + kr, no wrap (cb<=112, kr<16)
            if (BMODE == 2) {
                int sy = iy + ky - 1, sx = ix + kx - 1;
                bool pr = npred && sy >= 0 && sy < HH && sx >= 0 && sx < WW;
                int rowb = sy * WW + sx;
                #pragma unroll
                for (int i = 0; i < 8; i++) {
                    int kr = kb2 + 2 * i;
                    rb[i] = pr ? B[(size_t)(cb + kr) * P + rowb] : 0.f;
                }
            } else {
                int rowb = (iy + ky) * WW + (ix + kx);   // always in-bounds
                #pragma unroll
                for (int i = 0; i < 8; i++) {
                    int kr = kb2 + 2 * i;
                    rb[i] = npred ? B[(size_t)(cb + kr) * P + rowb] : 0.f;
                }
            }
        }
    };

    auto writeS = [&](int buf) {
        #pragma unroll
        for (int i = 0; i < 8; i++) As[buf][ka][ma + 8 * i] = ra[i];
        if (BMODE == 1) {
            #pragma unroll
            for (int i = 0; i < 8; i++) Bs[buf][kb16][(tid >> 4) + 8 * i] = rb[i];
        } else {
            #pragma unroll
            for (int i = 0; i < 8; i++) Bs[buf][kb2 + 2 * i][nb64] = rb[i];
        }
    };

    // prologue
    loadAB(0);
    writeS(0);
    __syncthreads();

    int buf = 0;
    for (int k0 = 0; k0 < K; k0 += 16) {
        bool nxt = (k0 + 16) < K;
        if (nxt) loadAB(k0 + 16);

        #pragma unroll
        for (int kk = 0; kk < 16; kk++) {
            float a[8], b[4];
            #pragma unroll
            for (int i = 0; i < 8; i++) a[i] = As[buf][kk][ty * 8 + i];
            #pragma unroll
            for (int j = 0; j < 4; j++) b[j] = Bs[buf][kk][tx * 4 + j];
            #pragma unroll
            for (int i = 0; i < 8; i++)
                #pragma unroll
                for (int j = 0; j < 4; j++) acc[i][j] += a[i] * b[j];
        }

        if (nxt) {
            writeS(buf ^ 1);
            __syncthreads();
            buf ^= 1;
        }
    }

    #pragma unroll
    for (int i = 0; i < 8; i++) {
        int gm = m0 + ty * 8 + i;
        float bv = (EPI >= 1) ? bias[gm] : 0.f;
        #pragma unroll
        for (int j = 0; j < 4; j++) {
            int gn = n0 + tx * 4 + j;
            if (gn < N) {
                float v2 = acc[i][j];
                if (EPI == 1) v2 += bv;
                if (EPI == 2) v2 = tanhf(v2 + bv);
                Cp[(size_t)gm * ldc + gn] = v2;
            }
        }
    }
}

// ============================================================
// gemm_big: scores[p][d] = sum_c q[c][p] * k[c][d]
// 128x128 tile, BK=8, 256 threads, 8x8 microtile, DOUBLE-buffered.
// ============================================================
__global__ void __launch_bounds__(256) gemm_big_k(
    const float* __restrict__ Aq,   // [C][P] per batch
    const float* __restrict__ Bk,   // [C][D] per batch
    float* __restrict__ Cs)         // [P][D] per batch
{
    __shared__ float As[2][8][132];
    __shared__ float Bs[2][8][132];
    const float* Ab = Aq + (size_t)blockIdx.z * C * P;
    const float* Bb = Bk + (size_t)blockIdx.z * C * D;
    float* Cb = Cs + (size_t)blockIdx.z * (size_t)P * D;

    const int m0 = blockIdx.y * 128, n0 = blockIdx.x * 128;
    const int tid = threadIdx.x;
    const int kf = tid >> 5, e4 = (tid & 31) * 4;
    const int tx = tid & 15, ty = tid >> 4;

    float acc[8][8];
    #pragma unroll
    for (int i = 0; i < 8; i++)
        #pragma unroll
        for (int j = 0; j < 8; j++) acc[i][j] = 0.f;

    float4 ra, rb;
    auto loadReg = [&](int k0) {
        const float* srcA = Ab + (size_t)(k0 + kf) * P;
        int m = m0 + e4;
        if (m + 3 < P) ra = *(const float4*)(srcA + m);
        else {
            ra.x = (m+0 < P) ? srcA[m+0] : 0.f;
            ra.y = (m+1 < P) ? srcA[m+1] : 0.f;
            ra.z = (m+2 < P) ? srcA[m+2] : 0.f;
            ra.w = (m+3 < P) ? srcA[m+3] : 0.f;
        }
        const float* srcB = Bb + (size_t)(k0 + kf) * D;
        int n = n0 + e4;
        if (n + 3 < D) rb = *(const float4*)(srcB + n);
        else {
            rb.x = (n+0 < D) ? srcB[n+0] : 0.f;
            rb.y = (n+1 < D) ? srcB[n+1] : 0.f;
            rb.z = (n+2 < D) ? srcB[n+2] : 0.f;
            rb.w = (n+3 < D) ? srcB[n+3] : 0.f;
        }
    };
    auto writeS = [&](int buf) {
        As[buf][kf][e4+0] = ra.x; As[buf][kf][e4+1] = ra.y;
        As[buf][kf][e4+2] = ra.z; As[buf][kf][e4+3] = ra.w;
        Bs[buf][kf][e4+0] = rb.x; Bs[buf][kf][e4+1] = rb.y;
        Bs[buf][kf][e4+2] = rb.z; Bs[buf][kf][e4+3] = rb.w;
    };

    loadReg(0);
    writeS(0);
    __syncthreads();

    int buf = 0;
    for (int k0 = 0; k0 < C; k0 += 8) {
        bool nxt = (k0 + 8) < C;
        if (nxt) loadReg(k0 + 8);

        #pragma unroll
        for (int kk = 0; kk < 8; kk++) {
            float a[8], b[8];
            #pragma unroll
            for (int r = 0; r < 4; r++) {
                a[r]     = As[buf][kk][ty * 4 + r];
                a[r + 4] = As[buf][kk][64 + ty * 4 + r];
                b[r]     = Bs[buf][kk][tx * 4 + r];
                b[r + 4] = Bs[buf][kk][64 + tx * 4 + r];
            }
            #pragma unroll
            for (int i = 0; i < 8; i++)
                #pragma unroll
                for (int j = 0; j < 8; j++) acc[i][j] += a[i] * b[j];
        }

        if (nxt) {
            writeS(buf ^ 1);
            __syncthreads();
            buf ^= 1;
        }
    }

    #pragma unroll
    for (int i = 0; i < 8; i++) {
        int gm = m0 + ((i < 4) ? (ty*4 + i) : (64 + ty*4 + i - 4));
        if (gm >= P) continue;
        #pragma unroll
        for (int j = 0; j < 8; j++) {
            int gn = n0 + ((j < 4) ? (tx*4 + j) : (64 + tx*4 + j - 4));
            if (gn < D)
                Cb[(size_t)gm * D + gn] = acc[i][j];
        }
    }
}

// -------- row softmax over D (proven; normalizes in place) --------
__global__ void softmax_k(float* __restrict__ sc)
{
    int n = blockIdx.z, qr = blockIdx.x;
    float* row = sc + ((size_t)n * P + qr) * D;
    __shared__ float red[256];
    int tid = threadIdx.x;
    float m = -1e30f;
    for (int d = tid; d < D; d += 256) m = fmaxf(m, row[d]);
    red[tid] = m; __syncthreads();
    for (int s = 128; s > 0; s >>= 1) { if (tid < s) red[tid] = fmaxf(red[tid], red[tid + s]); __syncthreads(); }
    m = red[0]; __syncthreads();
    float sum = 0.f;
    for (int d = tid; d < D; d += 256) { float e = __expf(row[d] - m); row[d] = e; sum += e; }
    red[tid] = sum; __syncthreads();
    for (int s = 128; s > 0; s >>= 1) { if (tid < s) red[tid] += red[tid + s]; __syncthreads(); }
    float inv = 1.0f / red[0];
    for (int d = tid; d < D; d += 256) row[d] *= inv;
}

// -------- beff = b_h + W_h[:,2C:3C] @ v_c; v_c from constant c0 --------
__global__ void beff_k(const float* __restrict__ w_vc, const float* __restrict__ c0,
                       const float* __restrict__ w_h, const float* __restrict__ b_h,
                       float* __restrict__ beff)
{
    __shared__ float vc[C];
    int c = threadIdx.x;  // 128 threads
    float s = 0.f;
    for (int ci = 0; ci < C; ci++) {
        float ws = 0.f;
        #pragma unroll
        for (int t = 0; t < 9; t++) ws += w_vc[((size_t)c * C + ci) * 9 + t];
        s += ws * c0[ci];
    }
    vc[c] = s;
    __syncthreads();
    float r = b_h[c];
    for (int j = 0; j < C; j++) r += w_h[(size_t)c * (3*C) + 2*C + j] * vc[j];
    beff[c] = r;
}

extern "C" void kernel_launch(void* const* d_in, const int* in_sizes, int n_in,
                              void* d_out, int out_size)
{
    const float* inp  = (const float*)d_in[0];
    const float* c0   = (const float*)d_in[1];
    const float* w_x  = (const float*)d_in[2];
    const float* b_x  = (const float*)d_in[3];
    const float* w_qx = (const float*)d_in[4];
    const float* w_kx = (const float*)d_in[6];
    const float* w_vx = (const float*)d_in[8];
    const float* w_vc = (const float*)d_in[9];
    const float* w_h  = (const float*)d_in[14];
    const float* b_h  = (const float*)d_in[15];
    const float* w_o  = (const float*)d_in[16];
    const float* b_o  = (const float*)d_in[17];
    float* out = (float*)d_out;

    float *xa, *q, *k, *v, *sc, *h, *beff;
    cudaGetSymbolAddress((void**)&xa,   g_xa);
    cudaGetSymbolAddress((void**)&q,    g_q);
    cudaGetSymbolAddress((void**)&k,    g_k);
    cudaGetSymbolAddress((void**)&v,    g_v);
    cudaGetSymbolAddress((void**)&sc,   g_sc);
    cudaGetSymbolAddress((void**)&h,    g_h);
    cudaGetSymbolAddress((void**)&beff, g_beff);

    const int NT_P = (P + 63) / 64;   // 21
    const int NT_D = (D + 63) / 64;   // 19

    // folded constant bias for proj_h (v_c branch)
    beff_k<<<1, C>>>(w_vc, c0, w_h, b_h, beff);

    // x = W_x @ inp + b_x  -> g_xa rows [0,128)
    gemm64_k<0,1><<<dim3(NT_P, 2, NB), 128>>>(
        w_x, 0, C, inp, (size_t)C*P, P, xa, (size_t)2*C*P, P, P, C, b_x);

    // q/k/v 3x3 convs with fused im2col (A = shared weights, sA = 0)
    gemm64_k<2,0><<<dim3(NT_P, 2, NB), 128>>>(
        w_qx, 0, KC, xa, (size_t)2*C*P, 0, q, (size_t)C*P, P, P, KC, b_x);
    gemm64_k<3,0><<<dim3(NT_D, 2, NB), 128>>>(
        w_kx, 0, KC, xa, (size_t)2*C*P, 0, k, (size_t)C*D, D, D, KC, b_x);
    gemm64_k<3,0><<<dim3(NT_D, 2, NB), 128>>>(
        w_vx, 0, KC, xa, (size_t)2*C*P, 0, v, (size_t)C*D, D, D, KC, b_x);

    // scores[p,d] = q^T k
    gemm_big_k<<<dim3((D + 127)/128, (P + 127)/128, NB), 256>>>(q, k, sc);

    // softmax rows (normalize in place)
    softmax_k<<<dim3(P, 1, NB), 256>>>(sc);

    // a0[c,p] = v @ probs^T  -> g_xa rows [128,256)   (A = per-batch v, sA = C*D)
    gemm64_k<1,0><<<dim3(NT_P, 2, NB), 128>>>(
        v, (size_t)C*D, D, sc, (size_t)P*D, D, xa + (size_t)C*P, (size_t)2*C*P, P, P, D, b_x);

    // h = tanh(W_h[:, :2C] @ [x; a0] + beff)
    gemm64_k<0,2><<<dim3(NT_P, 2, NB), 128>>>(
        w_h, 0, 3*C, xa, (size_t)2*C*P, P, h, (size_t)C*P, P, P, 2*C, beff);

    // out = W_o @ h + b_o
    gemm64_k<0,1><<<dim3(NT_P, 2, NB), 128>>>(
        w_o, 0, C, h, (size_t)C*P, P, out, (size_t)C*P, P, P, C, b_o);
}

// round 7
// speedup vs baseline: 1.7610x; 1.0600x over previous
#include <cuda_runtime.h>
#include <cstdint>
#include <cstddef>

// Problem dims
#define NB 8
#define C 128
#define HH 36
#define WW 36
#define P (HH*WW)          // 1296 query tokens
#define HV 34
#define WV 34
#define D (HV*WV)          // 1156 key/value tokens
#define KC (C*9)           // 1152 im2col K

// -------- scratch (static device memory; no allocation APIs) --------
__device__ float g_xa[(size_t)NB*2*C*P];     // rows 0..127: x, rows 128..255: a0
__device__ float g_q[(size_t)NB*C*P];
__device__ float g_k[(size_t)NB*C*D];
__device__ float g_v[(size_t)NB*C*D];
__device__ float g_sc[(size_t)NB*(size_t)P*D]; // scores -> probs in place
__device__ float g_h[(size_t)NB*C*P];
__device__ float g_beff[C];

// ============================================================
// qkv_mega: all three 3x3 conv GEMMs in ONE launch.
// Flattened tile map per batch (blockIdx.z = batch):
//   blockIdx.x in [0,42):   q-conv (SAME):  my = x/21 (2 M-tiles), nx = x%21
//   blockIdx.x in [42,118): k/v-conv (VALID): t2 = x-42, my = t2/19 (0..3), nx = t2%19
//       my 0..1 -> w_kx -> g_k ; my 2..3 -> w_vx -> g_v
// Inner pipeline identical to proven gemm64 (double-buffered, t-major K).
// ============================================================
__global__ void __launch_bounds__(128) qkv_mega_k(
    const float* __restrict__ xa,
    const float* __restrict__ w_qx,
    const float* __restrict__ w_kx,
    const float* __restrict__ w_vx,
    float* __restrict__ qo, float* __restrict__ ko, float* __restrict__ vo)
{
    __shared__ float As[2][16][68];
    __shared__ float Bs[2][16][68];

    const int bz = blockIdx.z;
    const int tile = blockIdx.x;
    bool qmode; int my, nx;
    if (tile < 42) { qmode = true;  my = tile / 21; nx = tile % 21; }
    else { int t2 = tile - 42; qmode = false; my = t2 / 19; nx = t2 % 19; }

    const float* A = qmode ? w_qx : ((my < 2) ? w_kx : w_vx);
    const int m0 = qmode ? my * 64 : (my & 1) * 64;
    const int Nn = qmode ? P : D;
    float* Cp = qmode ? (qo + (size_t)bz * C * P)
                      : ((my < 2) ? ko : vo) + (size_t)bz * C * D;
    const float* B = xa + (size_t)bz * 2 * C * P;   // x rows [0,128)
    const int n0 = nx * 64;
    const int ldc = Nn;

    const int tid = threadIdx.x;
    const int tx = tid & 15, ty = tid >> 4;

    const int ka = tid & 15;        // A slot: k fixed, m = (tid>>4)+8i
    const int ma = tid >> 4;
    const int nb64 = tid & 63;      // B slot: n fixed, k = (tid>>6)+2i
    const int kb2 = tid >> 6;

    // spatial coords of this thread's output column
    int p = n0 + nb64;
    bool npred; int iy, ix;
    if (qmode) { npred = (p < P); if (p >= P) p = 0; iy = p / WW; ix = p % WW; }
    else       { npred = (p < D); if (p >= D) p = 0; iy = p / WV; ix = p % WV; }

    float acc[8][4];
    #pragma unroll
    for (int i = 0; i < 8; i++)
        #pragma unroll
        for (int j = 0; j < 4; j++) acc[i][j] = 0.f;

    float ra[8], rb[8];

    auto loadAB = [&](int k0) {
        // A: t-major K order -> weight at [m][ci*9+t]
        int ci_a = (k0 + ka) & 127, t_a = (k0 + ka) >> 7;
        #pragma unroll
        for (int i = 0; i < 8; i++) {
            int m = m0 + ma + 8 * i;
            ra[i] = A[(size_t)m * KC + ci_a * 9 + t_a];
        }
        // B: gather from x
        int t = k0 >> 7;                    // constant within a 16-chunk
        int ky = t / 3, kx = t - ky * 3;
        int cb = k0 & 127;                  // ci = cb + kr, kr < 16, no wrap
        if (qmode) {
            int sy = iy + ky - 1, sx = ix + kx - 1;
            bool pr = npred && sy >= 0 && sy < HH && sx >= 0 && sx < WW;
            int rowb = sy * WW + sx;
            #pragma unroll
            for (int i = 0; i < 8; i++) {
                int kr = kb2 + 2 * i;
                rb[i] = pr ? B[(size_t)(cb + kr) * P + rowb] : 0.f;
            }
        } else {
            int rowb = (iy + ky) * WW + (ix + kx);
            #pragma unroll
            for (int i = 0; i < 8; i++) {
                int kr = kb2 + 2 * i;
                rb[i] = npred ? B[(size_t)(cb + kr) * P + rowb] : 0.f;
            }
        }
    };

    auto writeS = [&](int buf) {
        #pragma unroll
        for (int i = 0; i < 8; i++) As[buf][ka][ma + 8 * i] = ra[i];
        #pragma unroll
        for (int i = 0; i < 8; i++) Bs[buf][kb2 + 2 * i][nb64] = rb[i];
    };

    loadAB(0);
    writeS(0);
    __syncthreads();

    int buf = 0;
    for (int k0 = 0; k0 < KC; k0 += 16) {
        bool nxt = (k0 + 16) < KC;
        if (nxt) loadAB(k0 + 16);

        #pragma unroll
        for (int kk = 0; kk < 16; kk++) {
            float a[8], b[4];
            #pragma unroll
            for (int i = 0; i < 8; i++) a[i] = As[buf][kk][ty * 8 + i];
            #pragma unroll
            for (int j = 0; j < 4; j++) b[j] = Bs[buf][kk][tx * 4 + j];
            #pragma unroll
            for (int i = 0; i < 8; i++)
                #pragma unroll
                for (int j = 0; j < 4; j++) acc[i][j] += a[i] * b[j];
        }

        if (nxt) {
            writeS(buf ^ 1);
            __syncthreads();
            buf ^= 1;
        }
    }

    #pragma unroll
    for (int i = 0; i < 8; i++) {
        int gm = m0 + ty * 8 + i;
        #pragma unroll
        for (int j = 0; j < 4; j++) {
            int gn = n0 + tx * 4 + j;
            if (gn < Nn)
                Cp[(size_t)gm * ldc + gn] = acc[i][j];
        }
    }
}

// ============================================================
// gemm64: C[128,N] = A[128,K] @ B[K,N], 64x64 tile, 128 threads,
// 8x4 per-thread microtile. DOUBLE-BUFFERED.
// BMODE: 0 = B plain [K][N] (ldb), 1 = B transposed [N][K] (ldb)
// EPI: 0 none, 1 +bias[m], 2 tanh(acc+bias[m])
// ============================================================
template<int BMODE, int EPI>
__global__ void __launch_bounds__(128) gemm64_k(
    const float* __restrict__ A, size_t sA, int lda,
    const float* __restrict__ B, size_t sB, int ldb,
    float* __restrict__ Cp, size_t sC, int ldc,
    int N, int K,
    const float* __restrict__ bias)
{
    __shared__ float As[2][16][68];
    __shared__ float Bs[2][16][68];
    A  += (size_t)blockIdx.z * sA;
    B  += (size_t)blockIdx.z * sB;
    Cp += (size_t)blockIdx.z * sC;

    const int m0 = blockIdx.y * 64, n0 = blockIdx.x * 64;
    const int tid = threadIdx.x;
    const int tx = tid & 15, ty = tid >> 4;

    const int ka = tid & 15;
    const int ma = tid >> 4;
    const int nb64 = tid & 63;
    const int kb2 = tid >> 6;
    const int kb16 = tid & 15;

    float acc[8][4];
    #pragma unroll
    for (int i = 0; i < 8; i++)
        #pragma unroll
        for (int j = 0; j < 4; j++) acc[i][j] = 0.f;

    float ra[8], rb[8];

    auto loadAB = [&](int k0) {
        #pragma unroll
        for (int i = 0; i < 8; i++) {
            int gk = k0 + ka;
            int m = m0 + ma + 8 * i;
            ra[i] = (gk < K) ? A[(size_t)m * lda + gk] : 0.f;
        }
        if (BMODE == 0) {
            #pragma unroll
            for (int i = 0; i < 8; i++) {
                int gk = k0 + kb2 + 2 * i;
                int gn = n0 + nb64;
                rb[i] = (gn < N && gk < K) ? B[(size_t)gk * ldb + gn] : 0.f;
            }
        } else {
            #pragma unroll
            for (int i = 0; i < 8; i++) {
                int gn = n0 + (tid >> 4) + 8 * i;
                int gk = k0 + kb16;
                rb[i] = (gn < N && gk < K) ? B[(size_t)gn * ldb + gk] : 0.f;
            }
        }
    };

    auto writeS = [&](int buf) {
        #pragma unroll
        for (int i = 0; i < 8; i++) As[buf][ka][ma + 8 * i] = ra[i];
        if (BMODE == 1) {
            #pragma unroll
            for (int i = 0; i < 8; i++) Bs[buf][kb16][(tid >> 4) + 8 * i] = rb[i];
        } else {
            #pragma unroll
            for (int i = 0; i < 8; i++) Bs[buf][kb2 + 2 * i][nb64] = rb[i];
        }
    };

    loadAB(0);
    writeS(0);
    __syncthreads();

    int buf = 0;
    for (int k0 = 0; k0 < K; k0 += 16) {
        bool nxt = (k0 + 16) < K;
        if (nxt) loadAB(k0 + 16);

        #pragma unroll
        for (int kk = 0; kk < 16; kk++) {
            float a[8], b[4];
            #pragma unroll
            for (int i = 0; i < 8; i++) a[i] = As[buf][kk][ty * 8 + i];
            #pragma unroll
            for (int j = 0; j < 4; j++) b[j] = Bs[buf][kk][tx * 4 + j];
            #pragma unroll
            for (int i = 0; i < 8; i++)
                #pragma unroll
                for (int j = 0; j < 4; j++) acc[i][j] += a[i] * b[j];
        }

        if (nxt) {
            writeS(buf ^ 1);
            __syncthreads();
            buf ^= 1;
        }
    }

    #pragma unroll
    for (int i = 0; i < 8; i++) {
        int gm = m0 + ty * 8 + i;
        float bv = (EPI >= 1) ? bias[gm] : 0.f;
        #pragma unroll
        for (int j = 0; j < 4; j++) {
            int gn = n0 + tx * 4 + j;
            if (gn < N) {
                float v2 = acc[i][j];
                if (EPI == 1) v2 += bv;
                if (EPI == 2) v2 = tanhf(v2 + bv);
                Cp[(size_t)gm * ldc + gn] = v2;
            }
        }
    }
}

// ============================================================
// gemm_big: scores[p][d] = sum_c q[c][p] * k[c][d]
// 128x128 tile, BK=8, 256 threads, 8x8 microtile, double-buffered.
// ============================================================
__global__ void __launch_bounds__(256) gemm_big_k(
    const float* __restrict__ Aq,   // [C][P] per batch
    const float* __restrict__ Bk,   // [C][D] per batch
    float* __restrict__ Cs)         // [P][D] per batch
{
    __shared__ float As[2][8][132];
    __shared__ float Bs[2][8][132];
    const float* Ab = Aq + (size_t)blockIdx.z * C * P;
    const float* Bb = Bk + (size_t)blockIdx.z * C * D;
    float* Cb = Cs + (size_t)blockIdx.z * (size_t)P * D;

    const int m0 = blockIdx.y * 128, n0 = blockIdx.x * 128;
    const int tid = threadIdx.x;
    const int kf = tid >> 5, e4 = (tid & 31) * 4;
    const int tx = tid & 15, ty = tid >> 4;

    float acc[8][8];
    #pragma unroll
    for (int i = 0; i < 8; i++)
        #pragma unroll
        for (int j = 0; j < 8; j++) acc[i][j] = 0.f;

    float4 ra, rb;
    auto loadReg = [&](int k0) {
        const float* srcA = Ab + (size_t)(k0 + kf) * P;
        int m = m0 + e4;
        if (m + 3 < P) ra = *(const float4*)(srcA + m);
        else {
            ra.x = (m+0 < P) ? srcA[m+0] : 0.f;
            ra.y = (m+1 < P) ? srcA[m+1] : 0.f;
            ra.z = (m+2 < P) ? srcA[m+2] : 0.f;
            ra.w = (m+3 < P) ? srcA[m+3] : 0.f;
        }
        const float* srcB = Bb + (size_t)(k0 + kf) * D;
        int n = n0 + e4;
        if (n + 3 < D) rb = *(const float4*)(srcB + n);
        else {
            rb.x = (n+0 < D) ? srcB[n+0] : 0.f;
            rb.y = (n+1 < D) ? srcB[n+1] : 0.f;
            rb.z = (n+2 < D) ? srcB[n+2] : 0.f;
            rb.w = (n+3 < D) ? srcB[n+3] : 0.f;
        }
    };
    auto writeS = [&](int buf) {
        As[buf][kf][e4+0] = ra.x; As[buf][kf][e4+1] = ra.y;
        As[buf][kf][e4+2] = ra.z; As[buf][kf][e4+3] = ra.w;
        Bs[buf][kf][e4+0] = rb.x; Bs[buf][kf][e4+1] = rb.y;
        Bs[buf][kf][e4+2] = rb.z; Bs[buf][kf][e4+3] = rb.w;
    };

    loadReg(0);
    writeS(0);
    __syncthreads();

    int buf = 0;
    for (int k0 = 0; k0 < C; k0 += 8) {
        bool nxt = (k0 + 8) < C;
        if (nxt) loadReg(k0 + 8);

        #pragma unroll
        for (int kk = 0; kk < 8; kk++) {
            float a[8], b[8];
            #pragma unroll
            for (int r = 0; r < 4; r++) {
                a[r]     = As[buf][kk][ty * 4 + r];
                a[r + 4] = As[buf][kk][64 + ty * 4 + r];
                b[r]     = Bs[buf][kk][tx * 4 + r];
                b[r + 4] = Bs[buf][kk][64 + tx * 4 + r];
            }
            #pragma unroll
            for (int i = 0; i < 8; i++)
                #pragma unroll
                for (int j = 0; j < 8; j++) acc[i][j] += a[i] * b[j];
        }

        if (nxt) {
            writeS(buf ^ 1);
            __syncthreads();
            buf ^= 1;
        }
    }

    #pragma unroll
    for (int i = 0; i < 8; i++) {
        int gm = m0 + ((i < 4) ? (ty*4 + i) : (64 + ty*4 + i - 4));
        if (gm >= P) continue;
        #pragma unroll
        for (int j = 0; j < 8; j++) {
            int gn = n0 + ((j < 4) ? (tx*4 + j) : (64 + tx*4 + j - 4));
            if (gn < D)
                Cb[(size_t)gm * D + gn] = acc[i][j];
        }
    }
}

// -------- row softmax over D (proven; normalizes in place) --------
__global__ void softmax_k(float* __restrict__ sc)
{
    int n = blockIdx.z, qr = blockIdx.x;
    float* row = sc + ((size_t)n * P + qr) * D;
    __shared__ float red[256];
    int tid = threadIdx.x;
    float m = -1e30f;
    for (int d = tid; d < D; d += 256) m = fmaxf(m, row[d]);
    red[tid] = m; __syncthreads();
    for (int s = 128; s > 0; s >>= 1) { if (tid < s) red[tid] = fmaxf(red[tid], red[tid + s]); __syncthreads(); }
    m = red[0]; __syncthreads();
    float sum = 0.f;
    for (int d = tid; d < D; d += 256) { float e = __expf(row[d] - m); row[d] = e; sum += e; }
    red[tid] = sum; __syncthreads();
    for (int s = 128; s > 0; s >>= 1) { if (tid < s) red[tid] += red[tid + s]; __syncthreads(); }
    float inv = 1.0f / red[0];
    for (int d = tid; d < D; d += 256) row[d] *= inv;
}

// -------- beff = b_h + W_h[:,2C:3C] @ v_c; v_c from constant c0 --------
__global__ void beff_k(const float* __restrict__ w_vc, const float* __restrict__ c0,
                       const float* __restrict__ w_h, const float* __restrict__ b_h,
                       float* __restrict__ beff)
{
    __shared__ float vc[C];
    int c = threadIdx.x;  // 128 threads
    float s = 0.f;
    for (int ci = 0; ci < C; ci++) {
        float ws = 0.f;
        #pragma unroll
        for (int t = 0; t < 9; t++) ws += w_vc[((size_t)c * C + ci) * 9 + t];
        s += ws * c0[ci];
    }
    vc[c] = s;
    __syncthreads();
    float r = b_h[c];
    for (int j = 0; j < C; j++) r += w_h[(size_t)c * (3*C) + 2*C + j] * vc[j];
    beff[c] = r;
}

extern "C" void kernel_launch(void* const* d_in, const int* in_sizes, int n_in,
                              void* d_out, int out_size)
{
    const float* inp  = (const float*)d_in[0];
    const float* c0   = (const float*)d_in[1];
    const float* w_x  = (const float*)d_in[2];
    const float* b_x  = (const float*)d_in[3];
    const float* w_qx = (const float*)d_in[4];
    const float* w_kx = (const float*)d_in[6];
    const float* w_vx = (const float*)d_in[8];
    const float* w_vc = (const float*)d_in[9];
    const float* w_h  = (const float*)d_in[14];
    const float* b_h  = (const float*)d_in[15];
    const float* w_o  = (const float*)d_in[16];
    const float* b_o  = (const float*)d_in[17];
    float* out = (float*)d_out;

    float *xa, *q, *k, *v, *sc, *h, *beff;
    cudaGetSymbolAddress((void**)&xa,   g_xa);
    cudaGetSymbolAddress((void**)&q,    g_q);
    cudaGetSymbolAddress((void**)&k,    g_k);
    cudaGetSymbolAddress((void**)&v,    g_v);
    cudaGetSymbolAddress((void**)&sc,   g_sc);
    cudaGetSymbolAddress((void**)&h,    g_h);
    cudaGetSymbolAddress((void**)&beff, g_beff);

    const int NT_P = (P + 63) / 64;   // 21

    // folded constant bias for proj_h (v_c branch)
    beff_k<<<1, C>>>(w_vc, c0, w_h, b_h, beff);

    // x = W_x @ inp + b_x  -> g_xa rows [0,128)
    gemm64_k<0,1><<<dim3(NT_P, 2, NB), 128>>>(
        w_x, 0, C, inp, (size_t)C*P, P, xa, (size_t)2*C*P, P, P, C, b_x);

    // q/k/v 3x3 convs, single mega-launch (42 q-tiles + 76 kv-tiles per batch)
    qkv_mega_k<<<dim3(118, 1, NB), 128>>>(xa, w_qx, w_kx, w_vx, q, k, v);

    // scores[p,d] = q^T k
    gemm_big_k<<<dim3((D + 127)/128, (P + 127)/128, NB), 256>>>(q, k, sc);

    // softmax rows (normalize in place)
    softmax_k<<<dim3(P, 1, NB), 256>>>(sc);

    // a0[c,p] = v @ probs^T  -> g_xa rows [128,256)   (A = per-batch v, sA = C*D)
    gemm64_k<1,0><<<dim3(NT_P, 2, NB), 128>>>(
        v, (size_t)C*D, D, sc, (size_t)P*D, D, xa + (size_t)C*P, (size_t)2*C*P, P, P, D, b_x);

    // h = tanh(W_h[:, :2C] @ [x; a0] + beff)
    gemm64_k<0,2><<<dim3(NT_P, 2, NB), 128>>>(
        w_h, 0, 3*C, xa, (size_t)2*C*P, P, h, (size_t)C*P, P, P, 2*C, beff);

    // out = W_o @ h + b_o
    gemm64_k<0,1><<<dim3(NT_P, 2, NB), 128>>>(
        w_o, 0, C, h, (size_t)C*P, P, out, (size_t)C*P, P, P, C, b_o);
}

// round 8
// speedup vs baseline: 2.3017x; 1.3070x over previous
#include <cuda_runtime.h>
#include <cstdint>
#include <cstddef>

// Problem dims
#define NB 8
#define C 128
#define HH 36
#define WW 36
#define P (HH*WW)          // 1296 query tokens
#define HV 34
#define WV 34
#define D (HV*WV)          // 1156 key/value tokens
#define KC (C*9)           // 1152 im2col K

// -------- scratch (static device memory; no allocation APIs) --------
__device__ float g_xa[(size_t)NB*2*C*P];     // rows 0..127: x, rows 128..255: a0
__device__ float g_q[(size_t)NB*C*P];
__device__ float g_k[(size_t)NB*C*D];
__device__ float g_v[(size_t)NB*C*D];
__device__ float g_sc[(size_t)NB*(size_t)P*D]; // scores -> probs in place
__device__ float g_h[(size_t)NB*C*P];
__device__ float g_beff[C];

// -------- tf32 helpers --------
__device__ __forceinline__ uint32_t f2tf32(float f) {
    uint32_t u;
    asm("cvt.rna.tf32.f32 %0, %1;" : "=r"(u) : "f"(f));
    return u;
}

__device__ __forceinline__ void mma_tf32(
    float& c0, float& c1, float& c2, float& c3,
    uint32_t a0, uint32_t a1, uint32_t a2, uint32_t a3,
    uint32_t b0, uint32_t b1)
{
    asm volatile(
        "mma.sync.aligned.m16n8k8.row.col.f32.tf32.tf32.f32 "
        "{%0,%1,%2,%3}, {%4,%5,%6,%7}, {%8,%9}, {%0,%1,%2,%3};"
        : "+f"(c0), "+f"(c1), "+f"(c2), "+f"(c3)
        : "r"(a0), "r"(a1), "r"(a2), "r"(a3), "r"(b0), "r"(b1));
}

// ============================================================
// qkv_mega: all three 3x3 conv GEMMs in ONE launch, tf32 MMA core.
// Tile map per batch: blockIdx.x<42: q (SAME); else k/v (VALID).
// SMEM layout (proven loaders): As[k][m] (tf32 bits), Bs[k][n].
// CTA 64x64, 128 threads = 4 warps; warp tile 32x32
// (wm=warp&1 -> m half, wn=warp>>1 -> n half; mt in 0..1 m16, nt in 0..3 n8).
// ============================================================
__global__ void __launch_bounds__(128) qkv_mega_k(
    const float* __restrict__ xa,
    const float* __restrict__ w_qx,
    const float* __restrict__ w_kx,
    const float* __restrict__ w_vx,
    float* __restrict__ qo, float* __restrict__ ko, float* __restrict__ vo)
{
    __shared__ uint32_t As[2][16][68];
    __shared__ uint32_t Bs[2][16][68];

    const int bz = blockIdx.z;
    const int tile = blockIdx.x;
    bool qmode; int my, nx;
    if (tile < 42) { qmode = true;  my = tile / 21; nx = tile % 21; }
    else { int t2 = tile - 42; qmode = false; my = t2 / 19; nx = t2 % 19; }

    const float* A = qmode ? w_qx : ((my < 2) ? w_kx : w_vx);
    const int m0 = qmode ? my * 64 : (my & 1) * 64;
    const int Nn = qmode ? P : D;
    float* Cp = qmode ? (qo + (size_t)bz * C * P)
                      : ((my < 2) ? ko : vo) + (size_t)bz * C * D;
    const float* B = xa + (size_t)bz * 2 * C * P;   // x rows [0,128)
    const int n0 = nx * 64;
    const int ldc = Nn;

    const int tid = threadIdx.x;
    const int warp = tid >> 5, lane = tid & 31;
    const int g = lane >> 2, t = lane & 3;
    const int wm = warp & 1, wn = warp >> 1;
    const int m0w = wm * 32, n0w = wn * 32;

    const int ka = tid & 15;        // A slot: k fixed, m = (tid>>4)+8i
    const int ma = tid >> 4;
    const int nb64 = tid & 63;      // B slot: n fixed, k = (tid>>6)+2i
    const int kb2 = tid >> 6;

    // spatial coords of this thread's output column (loader)
    int p = n0 + nb64;
    bool npred; int iy, ix;
    if (qmode) { npred = (p < P); if (p >= P) p = 0; iy = p / WW; ix = p % WW; }
    else       { npred = (p < D); if (p >= D) p = 0; iy = p / WV; ix = p % WV; }

    float acc[2][4][4];
    #pragma unroll
    for (int i = 0; i < 2; i++)
        #pragma unroll
        for (int j = 0; j < 4; j++)
            #pragma unroll
            for (int r = 0; r < 4; r++) acc[i][j][r] = 0.f;

    float ra[8], rb[8];

    auto loadAB = [&](int k0) {
        int ci_a = (k0 + ka) & 127, t_a = (k0 + ka) >> 7;
        #pragma unroll
        for (int i = 0; i < 8; i++) {
            int m = m0 + ma + 8 * i;
            ra[i] = A[(size_t)m * KC + ci_a * 9 + t_a];
        }
        int tt = k0 >> 7;
        int ky = tt / 3, kx = tt - ky * 3;
        int cb = k0 & 127;
        if (qmode) {
            int sy = iy + ky - 1, sx = ix + kx - 1;
            bool pr = npred && sy >= 0 && sy < HH && sx >= 0 && sx < WW;
            int rowb = sy * WW + sx;
            #pragma unroll
            for (int i = 0; i < 8; i++) {
                int kr = kb2 + 2 * i;
                rb[i] = pr ? B[(size_t)(cb + kr) * P + rowb] : 0.f;
            }
        } else {
            int rowb = (iy + ky) * WW + (ix + kx);
            #pragma unroll
            for (int i = 0; i < 8; i++) {
                int kr = kb2 + 2 * i;
                rb[i] = npred ? B[(size_t)(cb + kr) * P + rowb] : 0.f;
            }
        }
    };

    auto writeS = [&](int buf) {
        #pragma unroll
        for (int i = 0; i < 8; i++) As[buf][ka][ma + 8 * i] = f2tf32(ra[i]);
        #pragma unroll
        for (int i = 0; i < 8; i++) Bs[buf][kb2 + 2 * i][nb64] = f2tf32(rb[i]);
    };

    loadAB(0);
    writeS(0);
    __syncthreads();

    int buf = 0;
    for (int k0 = 0; k0 < KC; k0 += 16) {
        bool nxt = (k0 + 16) < KC;
        if (nxt) loadAB(k0 + 16);

        #pragma unroll
        for (int ks = 0; ks < 2; ks++) {
            int kb = ks * 8;
            uint32_t af[2][4], bf[4][2];
            #pragma unroll
            for (int mt = 0; mt < 2; mt++) {
                int mb = m0w + mt * 16 + g;
                af[mt][0] = As[buf][kb + t][mb];
                af[mt][1] = As[buf][kb + t][mb + 8];
                af[mt][2] = As[buf][kb + t + 4][mb];
                af[mt][3] = As[buf][kb + t + 4][mb + 8];
            }
            #pragma unroll
            for (int nt = 0; nt < 4; nt++) {
                int nb = n0w + nt * 8 + g;
                bf[nt][0] = Bs[buf][kb + t][nb];
                bf[nt][1] = Bs[buf][kb + t + 4][nb];
            }
            #pragma unroll
            for (int mt = 0; mt < 2; mt++)
                #pragma unroll
                for (int nt = 0; nt < 4; nt++)
                    mma_tf32(acc[mt][nt][0], acc[mt][nt][1], acc[mt][nt][2], acc[mt][nt][3],
                             af[mt][0], af[mt][1], af[mt][2], af[mt][3],
                             bf[nt][0], bf[nt][1]);
        }

        if (nxt) {
            writeS(buf ^ 1);
            __syncthreads();
            buf ^= 1;
        }
    }

    #pragma unroll
    for (int mt = 0; mt < 2; mt++) {
        int gm = m0 + m0w + mt * 16 + g;
        #pragma unroll
        for (int nt = 0; nt < 4; nt++) {
            int gn = n0 + n0w + nt * 8 + 2 * t;
            if (gn < Nn)     Cp[(size_t)gm * ldc + gn]           = acc[mt][nt][0];
            if (gn + 1 < Nn) Cp[(size_t)gm * ldc + gn + 1]       = acc[mt][nt][1];
            if (gn < Nn)     Cp[(size_t)(gm + 8) * ldc + gn]     = acc[mt][nt][2];
            if (gn + 1 < Nn) Cp[(size_t)(gm + 8) * ldc + gn + 1] = acc[mt][nt][3];
        }
    }
}

// ============================================================
// gemm64t: tf32 MMA version of the 64x64 GEMM (used for PV).
// C[128,N] = A[128,K] @ B[K,N].
// BMODE: 0 = B plain [K][N], 1 = B transposed [N][K].
// EPI: 0 none, 1 +bias[m], 2 tanh(acc+bias[m])
// ============================================================
template<int BMODE, int EPI>
__global__ void __launch_bounds__(128) gemm64t_k(
    const float* __restrict__ A, size_t sA, int lda,
    const float* __restrict__ B, size_t sB, int ldb,
    float* __restrict__ Cp, size_t sC, int ldc,
    int N, int K,
    const float* __restrict__ bias)
{
    __shared__ uint32_t As[2][16][68];
    __shared__ uint32_t Bs[2][16][68];
    A  += (size_t)blockIdx.z * sA;
    B  += (size_t)blockIdx.z * sB;
    Cp += (size_t)blockIdx.z * sC;

    const int m0 = blockIdx.y * 64, n0 = blockIdx.x * 64;
    const int tid = threadIdx.x;
    const int warp = tid >> 5, lane = tid & 31;
    const int g = lane >> 2, t = lane & 3;
    const int wm = warp & 1, wn = warp >> 1;
    const int m0w = wm * 32, n0w = wn * 32;

    const int ka = tid & 15;
    const int ma = tid >> 4;
    const int nb64 = tid & 63;
    const int kb2 = tid >> 6;
    const int kb16 = tid & 15;

    float acc[2][4][4];
    #pragma unroll
    for (int i = 0; i < 2; i++)
        #pragma unroll
        for (int j = 0; j < 4; j++)
            #pragma unroll
            for (int r = 0; r < 4; r++) acc[i][j][r] = 0.f;

    float ra[8], rb[8];

    auto loadAB = [&](int k0) {
        #pragma unroll
        for (int i = 0; i < 8; i++) {
            int gk = k0 + ka;
            int m = m0 + ma + 8 * i;
            ra[i] = (gk < K) ? A[(size_t)m * lda + gk] : 0.f;
        }
        if (BMODE == 0) {
            #pragma unroll
            for (int i = 0; i < 8; i++) {
                int gk = k0 + kb2 + 2 * i;
                int gn = n0 + nb64;
                rb[i] = (gn < N && gk < K) ? B[(size_t)gk * ldb + gn] : 0.f;
            }
        } else {
            #pragma unroll
            for (int i = 0; i < 8; i++) {
                int gn = n0 + (tid >> 4) + 8 * i;
                int gk = k0 + kb16;
                rb[i] = (gn < N && gk < K) ? B[(size_t)gn * ldb + gk] : 0.f;
            }
        }
    };

    auto writeS = [&](int buf) {
        #pragma unroll
        for (int i = 0; i < 8; i++) As[buf][ka][ma + 8 * i] = f2tf32(ra[i]);
        if (BMODE == 1) {
            #pragma unroll
            for (int i = 0; i < 8; i++) Bs[buf][kb16][(tid >> 4) + 8 * i] = f2tf32(rb[i]);
        } else {
            #pragma unroll
            for (int i = 0; i < 8; i++) Bs[buf][kb2 + 2 * i][nb64] = f2tf32(rb[i]);
        }
    };

    loadAB(0);
    writeS(0);
    __syncthreads();

    int buf = 0;
    for (int k0 = 0; k0 < K; k0 += 16) {
        bool nxt = (k0 + 16) < K;
        if (nxt) loadAB(k0 + 16);

        #pragma unroll
        for (int ks = 0; ks < 2; ks++) {
            int kb = ks * 8;
            uint32_t af[2][4], bf[4][2];
            #pragma unroll
            for (int mt = 0; mt < 2; mt++) {
                int mb = m0w + mt * 16 + g;
                af[mt][0] = As[buf][kb + t][mb];
                af[mt][1] = As[buf][kb + t][mb + 8];
                af[mt][2] = As[buf][kb + t + 4][mb];
                af[mt][3] = As[buf][kb + t + 4][mb + 8];
            }
            #pragma unroll
            for (int nt = 0; nt < 4; nt++) {
                int nb = n0w + nt * 8 + g;
                bf[nt][0] = Bs[buf][kb + t][nb];
                bf[nt][1] = Bs[buf][kb + t + 4][nb];
            }
            #pragma unroll
            for (int mt = 0; mt < 2; mt++)
                #pragma unroll
                for (int nt = 0; nt < 4; nt++)
                    mma_tf32(acc[mt][nt][0], acc[mt][nt][1], acc[mt][nt][2], acc[mt][nt][3],
                             af[mt][0], af[mt][1], af[mt][2], af[mt][3],
                             bf[nt][0], bf[nt][1]);
        }

        if (nxt) {
            writeS(buf ^ 1);
            __syncthreads();
            buf ^= 1;
        }
    }

    #pragma unroll
    for (int mt = 0; mt < 2; mt++) {
        int gm = m0 + m0w + mt * 16 + g;
        float bv0 = (EPI >= 1) ? bias[gm] : 0.f;
        float bv8 = (EPI >= 1) ? bias[gm + 8] : 0.f;
        #pragma unroll
        for (int nt = 0; nt < 4; nt++) {
            int gn = n0 + n0w + nt * 8 + 2 * t;
            float v0 = acc[mt][nt][0], v1 = acc[mt][nt][1];
            float v2 = acc[mt][nt][2], v3 = acc[mt][nt][3];
            if (EPI == 1) { v0 += bv0; v1 += bv0; v2 += bv8; v3 += bv8; }
            if (EPI == 2) {
                v0 = tanhf(v0 + bv0); v1 = tanhf(v1 + bv0);
                v2 = tanhf(v2 + bv8); v3 = tanhf(v3 + bv8);
            }
            if (gn < N)     Cp[(size_t)gm * ldc + gn]           = v0;
            if (gn + 1 < N) Cp[(size_t)gm * ldc + gn + 1]       = v1;
            if (gn < N)     Cp[(size_t)(gm + 8) * ldc + gn]     = v2;
            if (gn + 1 < N) Cp[(size_t)(gm + 8) * ldc + gn + 1] = v3;
        }
    }
}

// ============================================================
// gemm64f: proven fp32 FFMA 64x64 GEMM (x-proj, proj_h, out —
// kept fp32 for precision headroom). BMODE 0 only used.
// ============================================================
template<int BMODE, int EPI>
__global__ void __launch_bounds__(128) gemm64f_k(
    const float* __restrict__ A, size_t sA, int lda,
    const float* __restrict__ B, size_t sB, int ldb,
    float* __restrict__ Cp, size_t sC, int ldc,
    int N, int K,
    const float* __restrict__ bias)
{
    __shared__ float As[2][16][68];
    __shared__ float Bs[2][16][68];
    A  += (size_t)blockIdx.z * sA;
    B  += (size_t)blockIdx.z * sB;
    Cp += (size_t)blockIdx.z * sC;

    const int m0 = blockIdx.y * 64, n0 = blockIdx.x * 64;
    const int tid = threadIdx.x;
    const int tx = tid & 15, ty = tid >> 4;

    const int ka = tid & 15;
    const int ma = tid >> 4;
    const int nb64 = tid & 63;
    const int kb2 = tid >> 6;
    const int kb16 = tid & 15;

    float acc[8][4];
    #pragma unroll
    for (int i = 0; i < 8; i++)
        #pragma unroll
        for (int j = 0; j < 4; j++) acc[i][j] = 0.f;

    float ra[8], rb[8];

    auto loadAB = [&](int k0) {
        #pragma unroll
        for (int i = 0; i < 8; i++) {
            int gk = k0 + ka;
            int m = m0 + ma + 8 * i;
            ra[i] = (gk < K) ? A[(size_t)m * lda + gk] : 0.f;
        }
        if (BMODE == 0) {
            #pragma unroll
            for (int i = 0; i < 8; i++) {
                int gk = k0 + kb2 + 2 * i;
                int gn = n0 + nb64;
                rb[i] = (gn < N && gk < K) ? B[(size_t)gk * ldb + gn] : 0.f;
            }
        } else {
            #pragma unroll
            for (int i = 0; i < 8; i++) {
                int gn = n0 + (tid >> 4) + 8 * i;
                int gk = k0 + kb16;
                rb[i] = (gn < N && gk < K) ? B[(size_t)gn * ldb + gk] : 0.f;
            }
        }
    };

    auto writeS = [&](int buf) {
        #pragma unroll
        for (int i = 0; i < 8; i++) As[buf][ka][ma + 8 * i] = ra[i];
        if (BMODE == 1) {
            #pragma unroll
            for (int i = 0; i < 8; i++) Bs[buf][kb16][(tid >> 4) + 8 * i] = rb[i];
        } else {
            #pragma unroll
            for (int i = 0; i < 8; i++) Bs[buf][kb2 + 2 * i][nb64] = rb[i];
        }
    };

    loadAB(0);
    writeS(0);
    __syncthreads();

    int buf = 0;
    for (int k0 = 0; k0 < K; k0 += 16) {
        bool nxt = (k0 + 16) < K;
        if (nxt) loadAB(k0 + 16);

        #pragma unroll
        for (int kk = 0; kk < 16; kk++) {
            float a[8], b[4];
            #pragma unroll
            for (int i = 0; i < 8; i++) a[i] = As[buf][kk][ty * 8 + i];
            #pragma unroll
            for (int j = 0; j < 4; j++) b[j] = Bs[buf][kk][tx * 4 + j];
            #pragma unroll
            for (int i = 0; i < 8; i++)
                #pragma unroll
                for (int j = 0; j < 4; j++) acc[i][j] += a[i] * b[j];
        }

        if (nxt) {
            writeS(buf ^ 1);
            __syncthreads();
            buf ^= 1;
        }
    }

    #pragma unroll
    for (int i = 0; i < 8; i++) {
        int gm = m0 + ty * 8 + i;
        float bv = (EPI >= 1) ? bias[gm] : 0.f;
        #pragma unroll
        for (int j = 0; j < 4; j++) {
            int gn = n0 + tx * 4 + j;
            if (gn < N) {
                float v2 = acc[i][j];
                if (EPI == 1) v2 += bv;
                if (EPI == 2) v2 = tanhf(v2 + bv);
                Cp[(size_t)gm * ldc + gn] = v2;
            }
        }
    }
}

// ============================================================
// gemm_big: scores[p][d] = sum_c q[c][p] * k[c][d], tf32 MMA core.
// CTA 128x128, 256 threads = 8 warps; warp tile 32(m) x 64(n):
// wm = warp&3, wn = warp>>2; mt in 0..1 (m16), nt in 0..7 (n8). BK=8.
// ============================================================
__global__ void __launch_bounds__(256) gemm_big_k(
    const float* __restrict__ Aq,   // [C][P] per batch
    const float* __restrict__ Bk,   // [C][D] per batch
    float* __restrict__ Cs)         // [P][D] per batch
{
    __shared__ uint32_t As[2][8][132];
    __shared__ uint32_t Bs[2][8][132];
    const float* Ab = Aq + (size_t)blockIdx.z * C * P;
    const float* Bb = Bk + (size_t)blockIdx.z * C * D;
    float* Cb = Cs + (size_t)blockIdx.z * (size_t)P * D;

    const int m0 = blockIdx.y * 128, n0 = blockIdx.x * 128;
    const int tid = threadIdx.x;
    const int kf = tid >> 5, e4 = (tid & 31) * 4;
    const int warp = tid >> 5, lane = tid & 31;
    const int g = lane >> 2, t = lane & 3;
    const int wm = warp & 3, wn = warp >> 2;
    const int m0w = wm * 32, n0w = wn * 64;

    float acc[2][8][4];
    #pragma unroll
    for (int i = 0; i < 2; i++)
        #pragma unroll
        for (int j = 0; j < 8; j++)
            #pragma unroll
            for (int r = 0; r < 4; r++) acc[i][j][r] = 0.f;

    float4 ra, rb;
    auto loadReg = [&](int k0) {
        const float* srcA = Ab + (size_t)(k0 + kf) * P;
        int m = m0 + e4;
        if (m + 3 < P) ra = *(const float4*)(srcA + m);
        else {
            ra.x = (m+0 < P) ? srcA[m+0] : 0.f;
            ra.y = (m+1 < P) ? srcA[m+1] : 0.f;
            ra.z = (m+2 < P) ? srcA[m+2] : 0.f;
            ra.w = (m+3 < P) ? srcA[m+3] : 0.f;
        }
        const float* srcB = Bb + (size_t)(k0 + kf) * D;
        int n = n0 + e4;
        if (n + 3 < D) rb = *(const float4*)(srcB + n);
        else {
            rb.x = (n+0 < D) ? srcB[n+0] : 0.f;
            rb.y = (n+1 < D) ? srcB[n+1] : 0.f;
            rb.z = (n+2 < D) ? srcB[n+2] : 0.f;
            rb.w = (n+3 < D) ? srcB[n+3] : 0.f;
        }
    };
    auto writeS = [&](int buf) {
        As[buf][kf][e4+0] = f2tf32(ra.x); As[buf][kf][e4+1] = f2tf32(ra.y);
        As[buf][kf][e4+2] = f2tf32(ra.z); As[buf][kf][e4+3] = f2tf32(ra.w);
        Bs[buf][kf][e4+0] = f2tf32(rb.x); Bs[buf][kf][e4+1] = f2tf32(rb.y);
        Bs[buf][kf][e4+2] = f2tf32(rb.z); Bs[buf][kf][e4+3] = f2tf32(rb.w);
    };

    loadReg(0);
    writeS(0);
    __syncthreads();

    int buf = 0;
    for (int k0 = 0; k0 < C; k0 += 8) {
        bool nxt = (k0 + 8) < C;
        if (nxt) loadReg(k0 + 8);

        {
            uint32_t af[2][4], bf[8][2];
            #pragma unroll
            for (int mt = 0; mt < 2; mt++) {
                int mb = m0w + mt * 16 + g;
                af[mt][0] = As[buf][t][mb];
                af[mt][1] = As[buf][t][mb + 8];
                af[mt][2] = As[buf][t + 4][mb];
                af[mt][3] = As[buf][t + 4][mb + 8];
            }
            #pragma unroll
            for (int nt = 0; nt < 8; nt++) {
                int nb = n0w + nt * 8 + g;
                bf[nt][0] = Bs[buf][t][nb];
                bf[nt][1] = Bs[buf][t + 4][nb];
            }
            #pragma unroll
            for (int mt = 0; mt < 2; mt++)
                #pragma unroll
                for (int nt = 0; nt < 8; nt++)
                    mma_tf32(acc[mt][nt][0], acc[mt][nt][1], acc[mt][nt][2], acc[mt][nt][3],
                             af[mt][0], af[mt][1], af[mt][2], af[mt][3],
                             bf[nt][0], bf[nt][1]);
        }

        if (nxt) {
            writeS(buf ^ 1);
            __syncthreads();
            buf ^= 1;
        }
    }

    #pragma unroll
    for (int mt = 0; mt < 2; mt++) {
        int gm = m0 + m0w + mt * 16 + g;
        #pragma unroll
        for (int nt = 0; nt < 8; nt++) {
            int gn = n0 + n0w + nt * 8 + 2 * t;
            if (gm < P) {
                if (gn < D)     Cb[(size_t)gm * D + gn]     = acc[mt][nt][0];
                if (gn + 1 < D) Cb[(size_t)gm * D + gn + 1] = acc[mt][nt][1];
            }
            if (gm + 8 < P) {
                if (gn < D)     Cb[(size_t)(gm + 8) * D + gn]     = acc[mt][nt][2];
                if (gn + 1 < D) Cb[(size_t)(gm + 8) * D + gn + 1] = acc[mt][nt][3];
            }
        }
    }
}

// -------- row softmax over D (proven; normalizes in place) --------
__global__ void softmax_k(float* __restrict__ sc)
{
    int n = blockIdx.z, qr = blockIdx.x;
    float* row = sc + ((size_t)n * P + qr) * D;
    __shared__ float red[256];
    int tid = threadIdx.x;
    float m = -1e30f;
    for (int d = tid; d < D; d += 256) m = fmaxf(m, row[d]);
    red[tid] = m; __syncthreads();
    for (int s = 128; s > 0; s >>= 1) { if (tid < s) red[tid] = fmaxf(red[tid], red[tid + s]); __syncthreads(); }
    m = red[0]; __syncthreads();
    float sum = 0.f;
    for (int d = tid; d < D; d += 256) { float e = __expf(row[d] - m); row[d] = e; sum += e; }
    red[tid] = sum; __syncthreads();
    for (int s = 128; s > 0; s >>= 1) { if (tid < s) red[tid] += red[tid + s]; __syncthreads(); }
    float inv = 1.0f / red[0];
    for (int d = tid; d < D; d += 256) row[d] *= inv;
}

// -------- beff = b_h + W_h[:,2C:3C] @ v_c; v_c from constant c0 --------
__global__ void beff_k(const float* __restrict__ w_vc, const float* __restrict__ c0,
                       const float* __restrict__ w_h, const float* __restrict__ b_h,
                       float* __restrict__ beff)
{
    __shared__ float vc[C];
    int c = threadIdx.x;  // 128 threads
    float s = 0.f;
    for (int ci = 0; ci < C; ci++) {
        float ws = 0.f;
        #pragma unroll
        for (int t = 0; t < 9; t++) ws += w_vc[((size_t)c * C + ci) * 9 + t];
        s += ws * c0[ci];
    }
    vc[c] = s;
    __syncthreads();
    float r = b_h[c];
    for (int j = 0; j < C; j++) r += w_h[(size_t)c * (3*C) + 2*C + j] * vc[j];
    beff[c] = r;
}

extern "C" void kernel_launch(void* const* d_in, const int* in_sizes, int n_in,
                              void* d_out, int out_size)
{
    const float* inp  = (const float*)d_in[0];
    const float* c0   = (const float*)d_in[1];
    const float* w_x  = (const float*)d_in[2];
    const float* b_x  = (const float*)d_in[3];
    const float* w_qx = (const float*)d_in[4];
    const float* w_kx = (const float*)d_in[6];
    const float* w_vx = (const float*)d_in[8];
    const float* w_vc = (const float*)d_in[9];
    const float* w_h  = (const float*)d_in[14];
    const float* b_h  = (const float*)d_in[15];
    const float* w_o  = (const float*)d_in[16];
    const float* b_o  = (const float*)d_in[17];
    float* out = (float*)d_out;

    float *xa, *q, *k, *v, *sc, *h, *beff;
    cudaGetSymbolAddress((void**)&xa,   g_xa);
    cudaGetSymbolAddress((void**)&q,    g_q);
    cudaGetSymbolAddress((void**)&k,    g_k);
    cudaGetSymbolAddress((void**)&v,    g_v);
    cudaGetSymbolAddress((void**)&sc,   g_sc);
    cudaGetSymbolAddress((void**)&h,    g_h);
    cudaGetSymbolAddress((void**)&beff, g_beff);

    const int NT_P = (P + 63) / 64;   // 21

    // folded constant bias for proj_h (v_c branch)
    beff_k<<<1, C>>>(w_vc, c0, w_h, b_h, beff);

    // x = W_x @ inp + b_x  (fp32 FFMA) -> g_xa rows [0,128)
    gemm64f_k<0,1><<<dim3(NT_P, 2, NB), 128>>>(
        w_x, 0, C, inp, (size_t)C*P, P, xa, (size_t)2*C*P, P, P, C, b_x);

    // q/k/v 3x3 convs, tf32 MMA mega-launch
    qkv_mega_k<<<dim3(118, 1, NB), 128>>>(xa, w_qx, w_kx, w_vx, q, k, v);

    // scores[p,d] = q^T k  (tf32 MMA)
    gemm_big_k<<<dim3((D + 127)/128, (P + 127)/128, NB), 256>>>(q, k, sc);

    // softmax rows (normalize in place)
    softmax_k<<<dim3(P, 1, NB), 256>>>(sc);

    // a0[c,p] = v @ probs^T  (tf32 MMA) -> g_xa rows [128,256)
    gemm64t_k<1,0><<<dim3(NT_P, 2, NB), 128>>>(
        v, (size_t)C*D, D, sc, (size_t)P*D, D, xa + (size_t)C*P, (size_t)2*C*P, P, P, D, b_x);

    // h = tanh(W_h[:, :2C] @ [x; a0] + beff)  (fp32 FFMA)
    gemm64f_k<0,2><<<dim3(NT_P, 2, NB), 128>>>(
        w_h, 0, 3*C, xa, (size_t)2*C*P, P, h, (size_t)C*P, P, P, 2*C, beff);

    // out = W_o @ h + b_o  (fp32 FFMA)
    gemm64f_k<0,1><<<dim3(NT_P, 2, NB), 128>>>(
        w_o, 0, C, h, (size_t)C*P, P, out, (size_t)C*P, P, P, C, b_o);
}

// round 9
// speedup vs baseline: 2.5157x; 1.0930x over previous
#include <cuda_runtime.h>
#include <cstdint>
#include <cstddef>

// Problem dims
#define NB 8
#define C 128
#define HH 36
#define WW 36
#define P (HH*WW)          // 1296 query tokens
#define HV 34
#define WV 34
#define D (HV*WV)          // 1156 key/value tokens
#define KC (C*9)           // 1152 im2col K

// -------- scratch (static device memory; no allocation APIs) --------
__device__ float g_xa[(size_t)NB*2*C*P];     // rows 0..127: x, rows 128..255: a0
__device__ float g_q[(size_t)NB*C*P];
__device__ float g_k[(size_t)NB*C*D];
__device__ float g_v[(size_t)NB*C*D];
__device__ float g_sc[(size_t)NB*(size_t)P*D]; // scores -> probs in place
__device__ float g_h[(size_t)NB*C*P];
__device__ float g_beff[C];

// -------- tf32 helpers --------
__device__ __forceinline__ uint32_t f2tf32(float f) {
    uint32_t u;
    asm("cvt.rna.tf32.f32 %0, %1;" : "=r"(u) : "f"(f));
    return u;
}

__device__ __forceinline__ void mma_tf32(
    float& c0, float& c1, float& c2, float& c3,
    uint32_t a0, uint32_t a1, uint32_t a2, uint32_t a3,
    uint32_t b0, uint32_t b1)
{
    asm volatile(
        "mma.sync.aligned.m16n8k8.row.col.f32.tf32.tf32.f32 "
        "{%0,%1,%2,%3}, {%4,%5,%6,%7}, {%8,%9}, {%0,%1,%2,%3};"
        : "+f"(c0), "+f"(c1), "+f"(c2), "+f"(c3)
        : "r"(a0), "r"(a1), "r"(a2), "r"(a3), "r"(b0), "r"(b1));
}

// ============================================================
// qkv_mega: all three 3x3 conv GEMMs in ONE launch, tf32 MMA core.
// Tile map per batch: blockIdx.x<42: q (SAME); else k/v (VALID).
// CTA 64x64, 128 threads = 4 warps; warp tile 32x32.
// SMEM rows padded to 72 u32 (72 mod 32 = 8 -> conflict-free frag loads).
// ============================================================
__global__ void __launch_bounds__(128) qkv_mega_k(
    const float* __restrict__ xa,
    const float* __restrict__ w_qx,
    const float* __restrict__ w_kx,
    const float* __restrict__ w_vx,
    float* __restrict__ qo, float* __restrict__ ko, float* __restrict__ vo)
{
    __shared__ uint32_t As[2][16][72];
    __shared__ uint32_t Bs[2][16][72];

    const int bz = blockIdx.z;
    const int tile = blockIdx.x;
    bool qmode; int my, nx;
    if (tile < 42) { qmode = true;  my = tile / 21; nx = tile % 21; }
    else { int t2 = tile - 42; qmode = false; my = t2 / 19; nx = t2 % 19; }

    const float* A = qmode ? w_qx : ((my < 2) ? w_kx : w_vx);
    const int m0 = qmode ? my * 64 : (my & 1) * 64;
    const int Nn = qmode ? P : D;
    float* Cp = qmode ? (qo + (size_t)bz * C * P)
                      : ((my < 2) ? ko : vo) + (size_t)bz * C * D;
    const float* B = xa + (size_t)bz * 2 * C * P;   // x rows [0,128)
    const int n0 = nx * 64;
    const int ldc = Nn;

    const int tid = threadIdx.x;
    const int warp = tid >> 5, lane = tid & 31;
    const int g = lane >> 2, t = lane & 3;
    const int wm = warp & 1, wn = warp >> 1;
    const int m0w = wm * 32, n0w = wn * 32;

    const int ka = tid & 15;        // A slot: k fixed, m = (tid>>4)+8i
    const int ma = tid >> 4;
    const int nb64 = tid & 63;      // B slot: n fixed, k = (tid>>6)+2i
    const int kb2 = tid >> 6;

    int p = n0 + nb64;
    bool npred; int iy, ix;
    if (qmode) { npred = (p < P); if (p >= P) p = 0; iy = p / WW; ix = p % WW; }
    else       { npred = (p < D); if (p >= D) p = 0; iy = p / WV; ix = p % WV; }

    float acc[2][4][4];
    #pragma unroll
    for (int i = 0; i < 2; i++)
        #pragma unroll
        for (int j = 0; j < 4; j++)
            #pragma unroll
            for (int r = 0; r < 4; r++) acc[i][j][r] = 0.f;

    float ra[8], rb[8];

    auto loadAB = [&](int k0) {
        int ci_a = (k0 + ka) & 127, t_a = (k0 + ka) >> 7;
        #pragma unroll
        for (int i = 0; i < 8; i++) {
            int m = m0 + ma + 8 * i;
            ra[i] = A[(size_t)m * KC + ci_a * 9 + t_a];
        }
        int tt = k0 >> 7;
        int ky = tt / 3, kx = tt - ky * 3;
        int cb = k0 & 127;
        if (qmode) {
            int sy = iy + ky - 1, sx = ix + kx - 1;
            bool pr = npred && sy >= 0 && sy < HH && sx >= 0 && sx < WW;
            int rowb = sy * WW + sx;
            #pragma unroll
            for (int i = 0; i < 8; i++) {
                int kr = kb2 + 2 * i;
                rb[i] = pr ? B[(size_t)(cb + kr) * P + rowb] : 0.f;
            }
        } else {
            int rowb = (iy + ky) * WW + (ix + kx);
            #pragma unroll
            for (int i = 0; i < 8; i++) {
                int kr = kb2 + 2 * i;
                rb[i] = npred ? B[(size_t)(cb + kr) * P + rowb] : 0.f;
            }
        }
    };

    auto writeS = [&](int buf) {
        #pragma unroll
        for (int i = 0; i < 8; i++) As[buf][ka][ma + 8 * i] = f2tf32(ra[i]);
        #pragma unroll
        for (int i = 0; i < 8; i++) Bs[buf][kb2 + 2 * i][nb64] = f2tf32(rb[i]);
    };

    loadAB(0);
    writeS(0);
    __syncthreads();

    int buf = 0;
    for (int k0 = 0; k0 < KC; k0 += 16) {
        bool nxt = (k0 + 16) < KC;
        if (nxt) loadAB(k0 + 16);

        #pragma unroll
        for (int ks = 0; ks < 2; ks++) {
            int kb = ks * 8;
            uint32_t af[2][4], bf[4][2];
            #pragma unroll
            for (int mt = 0; mt < 2; mt++) {
                int mb = m0w + mt * 16 + g;
                af[mt][0] = As[buf][kb + t][mb];
                af[mt][1] = As[buf][kb + t][mb + 8];
                af[mt][2] = As[buf][kb + t + 4][mb];
                af[mt][3] = As[buf][kb + t + 4][mb + 8];
            }
            #pragma unroll
            for (int nt = 0; nt < 4; nt++) {
                int nb = n0w + nt * 8 + g;
                bf[nt][0] = Bs[buf][kb + t][nb];
                bf[nt][1] = Bs[buf][kb + t + 4][nb];
            }
            #pragma unroll
            for (int mt = 0; mt < 2; mt++)
                #pragma unroll
                for (int nt = 0; nt < 4; nt++)
                    mma_tf32(acc[mt][nt][0], acc[mt][nt][1], acc[mt][nt][2], acc[mt][nt][3],
                             af[mt][0], af[mt][1], af[mt][2], af[mt][3],
                             bf[nt][0], bf[nt][1]);
        }

        if (nxt) {
            writeS(buf ^ 1);
            __syncthreads();
            buf ^= 1;
        }
    }

    #pragma unroll
    for (int mt = 0; mt < 2; mt++) {
        int gm = m0 + m0w + mt * 16 + g;
        #pragma unroll
        for (int nt = 0; nt < 4; nt++) {
            int gn = n0 + n0w + nt * 8 + 2 * t;
            if (gn < Nn)     Cp[(size_t)gm * ldc + gn]           = acc[mt][nt][0];
            if (gn + 1 < Nn) Cp[(size_t)gm * ldc + gn + 1]       = acc[mt][nt][1];
            if (gn < Nn)     Cp[(size_t)(gm + 8) * ldc + gn]     = acc[mt][nt][2];
            if (gn + 1 < Nn) Cp[(size_t)(gm + 8) * ldc + gn + 1] = acc[mt][nt][3];
        }
    }
}

// ============================================================
// gemm64t: tf32 MMA 64x64 GEMM. C[128,N] = A[128,K] @ B[K,N].
// BMODE: 0 = B plain [K][N], 1 = B transposed [N][K].
// EPI: 0 none, 1 +bias[m], 2 tanh(acc+bias[m])
// SMEM rows padded to 72 u32 (conflict-free).
// ============================================================
template<int BMODE, int EPI>
__global__ void __launch_bounds__(128) gemm64t_k(
    const float* __restrict__ A, size_t sA, int lda,
    const float* __restrict__ B, size_t sB, int ldb,
    float* __restrict__ Cp, size_t sC, int ldc,
    int N, int K,
    const float* __restrict__ bias)
{
    __shared__ uint32_t As[2][16][72];
    __shared__ uint32_t Bs[2][16][72];
    A  += (size_t)blockIdx.z * sA;
    B  += (size_t)blockIdx.z * sB;
    Cp += (size_t)blockIdx.z * sC;

    const int m0 = blockIdx.y * 64, n0 = blockIdx.x * 64;
    const int tid = threadIdx.x;
    const int warp = tid >> 5, lane = tid & 31;
    const int g = lane >> 2, t = lane & 3;
    const int wm = warp & 1, wn = warp >> 1;
    const int m0w = wm * 32, n0w = wn * 32;

    const int ka = tid & 15;
    const int ma = tid >> 4;
    const int nb64 = tid & 63;
    const int kb2 = tid >> 6;
    const int kb16 = tid & 15;

    float acc[2][4][4];
    #pragma unroll
    for (int i = 0; i < 2; i++)
        #pragma unroll
        for (int j = 0; j < 4; j++)
            #pragma unroll
            for (int r = 0; r < 4; r++) acc[i][j][r] = 0.f;

    float ra[8], rb[8];

    auto loadAB = [&](int k0) {
        #pragma unroll
        for (int i = 0; i < 8; i++) {
            int gk = k0 + ka;
            int m = m0 + ma + 8 * i;
            ra[i] = (gk < K) ? A[(size_t)m * lda + gk] : 0.f;
        }
        if (BMODE == 0) {
            #pragma unroll
            for (int i = 0; i < 8; i++) {
                int gk = k0 + kb2 + 2 * i;
                int gn = n0 + nb64;
                rb[i] = (gn < N && gk < K) ? B[(size_t)gk * ldb + gn] : 0.f;
            }
        } else {
            #pragma unroll
            for (int i = 0; i < 8; i++) {
                int gn = n0 + (tid >> 4) + 8 * i;
                int gk = k0 + kb16;
                rb[i] = (gn < N && gk < K) ? B[(size_t)gn * ldb + gk] : 0.f;
            }
        }
    };

    auto writeS = [&](int buf) {
        #pragma unroll
        for (int i = 0; i < 8; i++) As[buf][ka][ma + 8 * i] = f2tf32(ra[i]);
        if (BMODE == 1) {
            #pragma unroll
            for (int i = 0; i < 8; i++) Bs[buf][kb16][(tid >> 4) + 8 * i] = f2tf32(rb[i]);
        } else {
            #pragma unroll
            for (int i = 0; i < 8; i++) Bs[buf][kb2 + 2 * i][nb64] = f2tf32(rb[i]);
        }
    };

    loadAB(0);
    writeS(0);
    __syncthreads();

    int buf = 0;
    for (int k0 = 0; k0 < K; k0 += 16) {
        bool nxt = (k0 + 16) < K;
        if (nxt) loadAB(k0 + 16);

        #pragma unroll
        for (int ks = 0; ks < 2; ks++) {
            int kb = ks * 8;
            uint32_t af[2][4], bf[4][2];
            #pragma unroll
            for (int mt = 0; mt < 2; mt++) {
                int mb = m0w + mt * 16 + g;
                af[mt][0] = As[buf][kb + t][mb];
                af[mt][1] = As[buf][kb + t][mb + 8];
                af[mt][2] = As[buf][kb + t + 4][mb];
                af[mt][3] = As[buf][kb + t + 4][mb + 8];
            }
            #pragma unroll
            for (int nt = 0; nt < 4; nt++) {
                int nb = n0w + nt * 8 + g;
                bf[nt][0] = Bs[buf][kb + t][nb];
                bf[nt][1] = Bs[buf][kb + t + 4][nb];
            }
            #pragma unroll
            for (int mt = 0; mt < 2; mt++)
                #pragma unroll
                for (int nt = 0; nt < 4; nt++)
                    mma_tf32(acc[mt][nt][0], acc[mt][nt][1], acc[mt][nt][2], acc[mt][nt][3],
                             af[mt][0], af[mt][1], af[mt][2], af[mt][3],
                             bf[nt][0], bf[nt][1]);
        }

        if (nxt) {
            writeS(buf ^ 1);
            __syncthreads();
            buf ^= 1;
        }
    }

    #pragma unroll
    for (int mt = 0; mt < 2; mt++) {
        int gm = m0 + m0w + mt * 16 + g;
        float bv0 = (EPI >= 1) ? bias[gm] : 0.f;
        float bv8 = (EPI >= 1) ? bias[gm + 8] : 0.f;
        #pragma unroll
        for (int nt = 0; nt < 4; nt++) {
            int gn = n0 + n0w + nt * 8 + 2 * t;
            float v0 = acc[mt][nt][0], v1 = acc[mt][nt][1];
            float v2 = acc[mt][nt][2], v3 = acc[mt][nt][3];
            if (EPI == 1) { v0 += bv0; v1 += bv0; v2 += bv8; v3 += bv8; }
            if (EPI == 2) {
                v0 = tanhf(v0 + bv0); v1 = tanhf(v1 + bv0);
                v2 = tanhf(v2 + bv8); v3 = tanhf(v3 + bv8);
            }
            if (gn < N)     Cp[(size_t)gm * ldc + gn]           = v0;
            if (gn + 1 < N) Cp[(size_t)gm * ldc + gn + 1]       = v1;
            if (gn < N)     Cp[(size_t)(gm + 8) * ldc + gn]     = v2;
            if (gn + 1 < N) Cp[(size_t)(gm + 8) * ldc + gn + 1] = v3;
        }
    }
}

// ============================================================
// gemm_big: scores[p][d] = sum_c q[c][p] * k[c][d], tf32 MMA core.
// CTA 128x128, 256 threads = 8 warps; warp tile 32(m) x 64(n). BK=8.
// SMEM rows padded to 136 u32 (136 mod 32 = 8 -> conflict-free).
// ============================================================
__global__ void __launch_bounds__(256) gemm_big_k(
    const float* __restrict__ Aq,   // [C][P] per batch
    const float* __restrict__ Bk,   // [C][D] per batch
    float* __restrict__ Cs)         // [P][D] per batch
{
    __shared__ uint32_t As[2][8][136];
    __shared__ uint32_t Bs[2][8][136];
    const float* Ab = Aq + (size_t)blockIdx.z * C * P;
    const float* Bb = Bk + (size_t)blockIdx.z * C * D;
    float* Cb = Cs + (size_t)blockIdx.z * (size_t)P * D;

    const int m0 = blockIdx.y * 128, n0 = blockIdx.x * 128;
    const int tid = threadIdx.x;
    const int kf = tid >> 5, e4 = (tid & 31) * 4;
    const int warp = tid >> 5, lane = tid & 31;
    const int g = lane >> 2, t = lane & 3;
    const int wm = warp & 3, wn = warp >> 2;
    const int m0w = wm * 32, n0w = wn * 64;

    float acc[2][8][4];
    #pragma unroll
    for (int i = 0; i < 2; i++)
        #pragma unroll
        for (int j = 0; j < 8; j++)
            #pragma unroll
            for (int r = 0; r < 4; r++) acc[i][j][r] = 0.f;

    float4 ra, rb;
    auto loadReg = [&](int k0) {
        const float* srcA = Ab + (size_t)(k0 + kf) * P;
        int m = m0 + e4;
        if (m + 3 < P) ra = *(const float4*)(srcA + m);
        else {
            ra.x = (m+0 < P) ? srcA[m+0] : 0.f;
            ra.y = (m+1 < P) ? srcA[m+1] : 0.f;
            ra.z = (m+2 < P) ? srcA[m+2] : 0.f;
            ra.w = (m+3 < P) ? srcA[m+3] : 0.f;
        }
        const float* srcB = Bb + (size_t)(k0 + kf) * D;
        int n = n0 + e4;
        if (n + 3 < D) rb = *(const float4*)(srcB + n);
        else {
            rb.x = (n+0 < D) ? srcB[n+0] : 0.f;
            rb.y = (n+1 < D) ? srcB[n+1] : 0.f;
            rb.z = (n+2 < D) ? srcB[n+2] : 0.f;
            rb.w = (n+3 < D) ? srcB[n+3] : 0.f;
        }
    };
    auto writeS = [&](int buf) {
        As[buf][kf][e4+0] = f2tf32(ra.x); As[buf][kf][e4+1] = f2tf32(ra.y);
        As[buf][kf][e4+2] = f2tf32(ra.z); As[buf][kf][e4+3] = f2tf32(ra.w);
        Bs[buf][kf][e4+0] = f2tf32(rb.x); Bs[buf][kf][e4+1] = f2tf32(rb.y);
        Bs[buf][kf][e4+2] = f2tf32(rb.z); Bs[buf][kf][e4+3] = f2tf32(rb.w);
    };

    loadReg(0);
    writeS(0);
    __syncthreads();

    int buf = 0;
    for (int k0 = 0; k0 < C; k0 += 8) {
        bool nxt = (k0 + 8) < C;
        if (nxt) loadReg(k0 + 8);

        {
            uint32_t af[2][4], bf[8][2];
            #pragma unroll
            for (int mt = 0; mt < 2; mt++) {
                int mb = m0w + mt * 16 + g;
                af[mt][0] = As[buf][t][mb];
                af[mt][1] = As[buf][t][mb + 8];
                af[mt][2] = As[buf][t + 4][mb];
                af[mt][3] = As[buf][t + 4][mb + 8];
            }
            #pragma unroll
            for (int nt = 0; nt < 8; nt++) {
                int nb = n0w + nt * 8 + g;
                bf[nt][0] = Bs[buf][t][nb];
                bf[nt][1] = Bs[buf][t + 4][nb];
            }
            #pragma unroll
            for (int mt = 0; mt < 2; mt++)
                #pragma unroll
                for (int nt = 0; nt < 8; nt++)
                    mma_tf32(acc[mt][nt][0], acc[mt][nt][1], acc[mt][nt][2], acc[mt][nt][3],
                             af[mt][0], af[mt][1], af[mt][2], af[mt][3],
                             bf[nt][0], bf[nt][1]);
        }

        if (nxt) {
            writeS(buf ^ 1);
            __syncthreads();
            buf ^= 1;
        }
    }

    #pragma unroll
    for (int mt = 0; mt < 2; mt++) {
        int gm = m0 + m0w + mt * 16 + g;
        #pragma unroll
        for (int nt = 0; nt < 8; nt++) {
            int gn = n0 + n0w + nt * 8 + 2 * t;
            if (gm < P) {
                if (gn < D)     Cb[(size_t)gm * D + gn]     = acc[mt][nt][0];
                if (gn + 1 < D) Cb[(size_t)gm * D + gn + 1] = acc[mt][nt][1];
            }
            if (gm + 8 < P) {
                if (gn < D)     Cb[(size_t)(gm + 8) * D + gn]     = acc[mt][nt][2];
                if (gn + 1 < D) Cb[(size_t)(gm + 8) * D + gn + 1] = acc[mt][nt][3];
            }
        }
    }
}

// -------- row softmax over D (proven; normalizes in place) --------
__global__ void softmax_k(float* __restrict__ sc)
{
    int n = blockIdx.z, qr = blockIdx.x;
    float* row = sc + ((size_t)n * P + qr) * D;
    __shared__ float red[256];
    int tid = threadIdx.x;
    float m = -1e30f;
    for (int d = tid; d < D; d += 256) m = fmaxf(m, row[d]);
    red[tid] = m; __syncthreads();
    for (int s = 128; s > 0; s >>= 1) { if (tid < s) red[tid] = fmaxf(red[tid], red[tid + s]); __syncthreads(); }
    m = red[0]; __syncthreads();
    float sum = 0.f;
    for (int d = tid; d < D; d += 256) { float e = __expf(row[d] - m); row[d] = e; sum += e; }
    red[tid] = sum; __syncthreads();
    for (int s = 128; s > 0; s >>= 1) { if (tid < s) red[tid] += red[tid + s]; __syncthreads(); }
    float inv = 1.0f / red[0];
    for (int d = tid; d < D; d += 256) row[d] *= inv;
}

// -------- beff = b_h + W_h[:,2C:3C] @ v_c; v_c from constant c0 --------
__global__ void beff_k(const float* __restrict__ w_vc, const float* __restrict__ c0,
                       const float* __restrict__ w_h, const float* __restrict__ b_h,
                       float* __restrict__ beff)
{
    __shared__ float vc[C];
    int c = threadIdx.x;  // 128 threads
    float s = 0.f;
    for (int ci = 0; ci < C; ci++) {
        float ws = 0.f;
        #pragma unroll
        for (int t = 0; t < 9; t++) ws += w_vc[((size_t)c * C + ci) * 9 + t];
        s += ws * c0[ci];
    }
    vc[c] = s;
    __syncthreads();
    float r = b_h[c];
    for (int j = 0; j < C; j++) r += w_h[(size_t)c * (3*C) + 2*C + j] * vc[j];
    beff[c] = r;
}

extern "C" void kernel_launch(void* const* d_in, const int* in_sizes, int n_in,
                              void* d_out, int out_size)
{
    const float* inp  = (const float*)d_in[0];
    const float* c0   = (const float*)d_in[1];
    const float* w_x  = (const float*)d_in[2];
    const float* b_x  = (const float*)d_in[3];
    const float* w_qx = (const float*)d_in[4];
    const float* w_kx = (const float*)d_in[6];
    const float* w_vx = (const float*)d_in[8];
    const float* w_vc = (const float*)d_in[9];
    const float* w_h  = (const float*)d_in[14];
    const float* b_h  = (const float*)d_in[15];
    const float* w_o  = (const float*)d_in[16];
    const float* b_o  = (const float*)d_in[17];
    float* out = (float*)d_out;

    float *xa, *q, *k, *v, *sc, *h, *beff;
    cudaGetSymbolAddress((void**)&xa,   g_xa);
    cudaGetSymbolAddress((void**)&q,    g_q);
    cudaGetSymbolAddress((void**)&k,    g_k);
    cudaGetSymbolAddress((void**)&v,    g_v);
    cudaGetSymbolAddress((void**)&sc,   g_sc);
    cudaGetSymbolAddress((void**)&h,    g_h);
    cudaGetSymbolAddress((void**)&beff, g_beff);

    const int NT_P = (P + 63) / 64;   // 21

    // folded constant bias for proj_h (v_c branch)
    beff_k<<<1, C>>>(w_vc, c0, w_h, b_h, beff);

    // x = W_x @ inp + b_x  (tf32 MMA) -> g_xa rows [0,128)
    gemm64t_k<0,1><<<dim3(NT_P, 2, NB), 128>>>(
        w_x, 0, C, inp, (size_t)C*P, P, xa, (size_t)2*C*P, P, P, C, b_x);

    // q/k/v 3x3 convs, tf32 MMA mega-launch
    qkv_mega_k<<<dim3(118, 1, NB), 128>>>(xa, w_qx, w_kx, w_vx, q, k, v);

    // scores[p,d] = q^T k  (tf32 MMA)
    gemm_big_k<<<dim3((D + 127)/128, (P + 127)/128, NB), 256>>>(q, k, sc);

    // softmax rows (normalize in place)
    softmax_k<<<dim3(P, 1, NB), 256>>>(sc);

    // a0[c,p] = v @ probs^T  (tf32 MMA) -> g_xa rows [128,256)
    gemm64t_k<1,0><<<dim3(NT_P, 2, NB), 128>>>(
        v, (size_t)C*D, D, sc, (size_t)P*D, D, xa + (size_t)C*P, (size_t)2*C*P, P, P, D, b_x);

    // h = tanh(W_h[:, :2C] @ [x; a0] + beff)  (tf32 MMA)
    gemm64t_k<0,2><<<dim3(NT_P, 2, NB), 128>>>(
        w_h, 0, 3*C, xa, (size_t)2*C*P, P, h, (size_t)C*P, P, P, 2*C, beff);

    // out = W_o @ h + b_o  (tf32 MMA)
    gemm64t_k<0,1><<<dim3(NT_P, 2, NB), 128>>>(
        w_o, 0, C, h, (size_t)C*P, P, out, (size_t)C*P, P, P, C, b_o);
}

// round 10
// speedup vs baseline: 2.7133x; 1.0786x over previous
#include <cuda_runtime.h>
#include <cstdint>
#include <cstddef>

// Problem dims
#define NB 8
#define C 128
#define HH 36
#define WW 36
#define P (HH*WW)          // 1296 query tokens
#define HV 34
#define WV 34
#define D (HV*WV)          // 1156 key/value tokens
#define KC (C*9)           // 1152 im2col K

// -------- scratch (static device memory; no allocation APIs) --------
__device__ float g_xa[(size_t)NB*2*C*P];     // rows 0..127: x, rows 128..255: a0
__device__ float g_q[(size_t)NB*C*P];
__device__ float g_k[(size_t)NB*C*D];
__device__ float g_v[(size_t)NB*C*D];
__device__ float g_sc[(size_t)NB*(size_t)P*D]; // scores -> probs in place
__device__ float g_h[(size_t)NB*C*P];
__device__ float g_beff[C];

// -------- tf32 helpers --------
__device__ __forceinline__ uint32_t f2tf32(float f) {
    uint32_t u;
    asm("cvt.rna.tf32.f32 %0, %1;" : "=r"(u) : "f"(f));
    return u;
}

__device__ __forceinline__ void mma_tf32(
    float& c0, float& c1, float& c2, float& c3,
    uint32_t a0, uint32_t a1, uint32_t a2, uint32_t a3,
    uint32_t b0, uint32_t b1)
{
    asm volatile(
        "mma.sync.aligned.m16n8k8.row.col.f32.tf32.tf32.f32 "
        "{%0,%1,%2,%3}, {%4,%5,%6,%7}, {%8,%9}, {%0,%1,%2,%3};"
        : "+f"(c0), "+f"(c1), "+f"(c2), "+f"(c3)
        : "r"(a0), "r"(a1), "r"(a2), "r"(a3), "r"(b0), "r"(b1));
}

// ============================================================
// qkv_mega: all three 3x3 conv GEMMs in ONE launch, tf32 MMA core.
// CTA tile 64(m) x 128(n), 128 threads = 4 warps, warp tile 32x64.
// Tile map per batch (62 tiles):
//   tile <  22: q-conv (SAME):  my = tile/11 (0..1), nx = tile%11
//   tile >= 22: k/v (VALID): t2 = tile-22, my = t2/10 (0..3), nx = t2%10
//       my 0..1 -> w_kx -> g_k ; my 2..3 -> w_vx -> g_v
// K reordered t-major: kg = t*128 + ci; weight read at [m][ci*9+t].
// ============================================================
__global__ void __launch_bounds__(128) qkv_mega_k(
    const float* __restrict__ xa,
    const float* __restrict__ w_qx,
    const float* __restrict__ w_kx,
    const float* __restrict__ w_vx,
    float* __restrict__ qo, float* __restrict__ ko, float* __restrict__ vo)
{
    __shared__ uint32_t As[2][16][72];
    __shared__ uint32_t Bs[2][16][136];

    const int bz = blockIdx.z;
    const int tile = blockIdx.x;
    bool qmode; int my, nx;
    if (tile < 22) { qmode = true;  my = tile / 11; nx = tile % 11; }
    else { int t2 = tile - 22; qmode = false; my = t2 / 10; nx = t2 % 10; }

    const float* A = qmode ? w_qx : ((my < 2) ? w_kx : w_vx);
    const int m0 = qmode ? my * 64 : (my & 1) * 64;
    const int Nn = qmode ? P : D;
    float* Cp = qmode ? (qo + (size_t)bz * C * P)
                      : ((my < 2) ? ko : vo) + (size_t)bz * C * D;
    const float* B = xa + (size_t)bz * 2 * C * P;   // x rows [0,128)
    const int n0 = nx * 128;
    const int ldc = Nn;

    const int tid = threadIdx.x;
    const int warp = tid >> 5, lane = tid & 31;
    const int g = lane >> 2, t = lane & 3;
    const int wm = warp & 1, wn = warp >> 1;
    const int m0w = wm * 32, n0w = wn * 64;

    const int ka = tid & 15;        // A slot: k fixed, m = (tid>>4)+8i
    const int ma = tid >> 4;

    // B: this thread owns output column p = n0 + tid, all 16 k-rows.
    int p = n0 + tid;
    bool npred; int iy, ix;
    if (qmode) { npred = (p < P); if (p >= P) p = 0; iy = p / WW; ix = p % WW; }
    else       { npred = (p < D); if (p >= D) p = 0; iy = p / WV; ix = p % WV; }

    float acc[2][8][4];
    #pragma unroll
    for (int i = 0; i < 2; i++)
        #pragma unroll
        for (int j = 0; j < 8; j++)
            #pragma unroll
            for (int r = 0; r < 4; r++) acc[i][j][r] = 0.f;

    float ra[8], rb[16];

    auto loadAB = [&](int k0) {
        int ci_a = (k0 + ka) & 127, t_a = (k0 + ka) >> 7;
        #pragma unroll
        for (int i = 0; i < 8; i++) {
            int m = m0 + ma + 8 * i;
            ra[i] = A[(size_t)m * KC + ci_a * 9 + t_a];
        }
        int tt = k0 >> 7;                 // constant within a 16-chunk
        int ky = tt / 3, kx = tt - ky * 3;
        int cb = k0 & 127;                // ci = cb + i, i < 16, no wrap
        if (qmode) {
            int sy = iy + ky - 1, sx = ix + kx - 1;
            bool pr = npred && sy >= 0 && sy < HH && sx >= 0 && sx < WW;
            int rowb = sy * WW + sx;
            #pragma unroll
            for (int i = 0; i < 16; i++)
                rb[i] = pr ? B[(size_t)(cb + i) * P + rowb] : 0.f;
        } else {
            int rowb = (iy + ky) * WW + (ix + kx);
            #pragma unroll
            for (int i = 0; i < 16; i++)
                rb[i] = npred ? B[(size_t)(cb + i) * P + rowb] : 0.f;
        }
    };

    auto writeS = [&](int buf) {
        #pragma unroll
        for (int i = 0; i < 8; i++) As[buf][ka][ma + 8 * i] = f2tf32(ra[i]);
        #pragma unroll
        for (int i = 0; i < 16; i++) Bs[buf][i][tid] = f2tf32(rb[i]);
    };

    loadAB(0);
    writeS(0);
    __syncthreads();

    int buf = 0;
    for (int k0 = 0; k0 < KC; k0 += 16) {
        bool nxt = (k0 + 16) < KC;
        if (nxt) loadAB(k0 + 16);

        #pragma unroll
        for (int ks = 0; ks < 2; ks++) {
            int kb = ks * 8;
            uint32_t af[2][4], bf[8][2];
            #pragma unroll
            for (int mt = 0; mt < 2; mt++) {
                int mb = m0w + mt * 16 + g;
                af[mt][0] = As[buf][kb + t][mb];
                af[mt][1] = As[buf][kb + t][mb + 8];
                af[mt][2] = As[buf][kb + t + 4][mb];
                af[mt][3] = As[buf][kb + t + 4][mb + 8];
            }
            #pragma unroll
            for (int nt = 0; nt < 8; nt++) {
                int nb = n0w + nt * 8 + g;
                bf[nt][0] = Bs[buf][kb + t][nb];
                bf[nt][1] = Bs[buf][kb + t + 4][nb];
            }
            #pragma unroll
            for (int mt = 0; mt < 2; mt++)
                #pragma unroll
                for (int nt = 0; nt < 8; nt++)
                    mma_tf32(acc[mt][nt][0], acc[mt][nt][1], acc[mt][nt][2], acc[mt][nt][3],
                             af[mt][0], af[mt][1], af[mt][2], af[mt][3],
                             bf[nt][0], bf[nt][1]);
        }

        if (nxt) {
            writeS(buf ^ 1);
            __syncthreads();
            buf ^= 1;
        }
    }

    #pragma unroll
    for (int mt = 0; mt < 2; mt++) {
        int gm = m0 + m0w + mt * 16 + g;
        #pragma unroll
        for (int nt = 0; nt < 8; nt++) {
            int gn = n0 + n0w + nt * 8 + 2 * t;
            if (gn < Nn)     Cp[(size_t)gm * ldc + gn]           = acc[mt][nt][0];
            if (gn + 1 < Nn) Cp[(size_t)gm * ldc + gn + 1]       = acc[mt][nt][1];
            if (gn < Nn)     Cp[(size_t)(gm + 8) * ldc + gn]     = acc[mt][nt][2];
            if (gn + 1 < Nn) Cp[(size_t)(gm + 8) * ldc + gn + 1] = acc[mt][nt][3];
        }
    }
}

// ============================================================
// gemm64t: tf32 MMA 64x64 GEMM. C[128,N] = A[128,K] @ B[K,N].
// BMODE: 0 = B plain [K][N], 1 = B transposed [N][K].
// EPI: 0 none, 1 +bias[m], 2 tanh(acc+bias[m])
// ============================================================
template<int BMODE, int EPI>
__global__ void __launch_bounds__(128) gemm64t_k(
    const float* __restrict__ A, size_t sA, int lda,
    const float* __restrict__ B, size_t sB, int ldb,
    float* __restrict__ Cp, size_t sC, int ldc,
    int N, int K,
    const float* __restrict__ bias)
{
    __shared__ uint32_t As[2][16][72];
    __shared__ uint32_t Bs[2][16][72];
    A  += (size_t)blockIdx.z * sA;
    B  += (size_t)blockIdx.z * sB;
    Cp += (size_t)blockIdx.z * sC;

    const int m0 = blockIdx.y * 64, n0 = blockIdx.x * 64;
    const int tid = threadIdx.x;
    const int warp = tid >> 5, lane = tid & 31;
    const int g = lane >> 2, t = lane & 3;
    const int wm = warp & 1, wn = warp >> 1;
    const int m0w = wm * 32, n0w = wn * 32;

    const int ka = tid & 15;
    const int ma = tid >> 4;
    const int nb64 = tid & 63;
    const int kb2 = tid >> 6;
    const int kb16 = tid & 15;

    float acc[2][4][4];
    #pragma unroll
    for (int i = 0; i < 2; i++)
        #pragma unroll
        for (int j = 0; j < 4; j++)
            #pragma unroll
            for (int r = 0; r < 4; r++) acc[i][j][r] = 0.f;

    float ra[8], rb[8];

    auto loadAB = [&](int k0) {
        #pragma unroll
        for (int i = 0; i < 8; i++) {
            int gk = k0 + ka;
            int m = m0 + ma + 8 * i;
            ra[i] = (gk < K) ? A[(size_t)m * lda + gk] : 0.f;
        }
        if (BMODE == 0) {
            #pragma unroll
            for (int i = 0; i < 8; i++) {
                int gk = k0 + kb2 + 2 * i;
                int gn = n0 + nb64;
                rb[i] = (gn < N && gk < K) ? B[(size_t)gk * ldb + gn] : 0.f;
            }
        } else {
            #pragma unroll
            for (int i = 0; i < 8; i++) {
                int gn = n0 + (tid >> 4) + 8 * i;
                int gk = k0 + kb16;
                rb[i] = (gn < N && gk < K) ? B[(size_t)gn * ldb + gk] : 0.f;
            }
        }
    };

    auto writeS = [&](int buf) {
        #pragma unroll
        for (int i = 0; i < 8; i++) As[buf][ka][ma + 8 * i] = f2tf32(ra[i]);
        if (BMODE == 1) {
            #pragma unroll
            for (int i = 0; i < 8; i++) Bs[buf][kb16][(tid >> 4) + 8 * i] = f2tf32(rb[i]);
        } else {
            #pragma unroll
            for (int i = 0; i < 8; i++) Bs[buf][kb2 + 2 * i][nb64] = f2tf32(rb[i]);
        }
    };

    loadAB(0);
    writeS(0);
    __syncthreads();

    int buf = 0;
    for (int k0 = 0; k0 < K; k0 += 16) {
        bool nxt = (k0 + 16) < K;
        if (nxt) loadAB(k0 + 16);

        #pragma unroll
        for (int ks = 0; ks < 2; ks++) {
            int kb = ks * 8;
            uint32_t af[2][4], bf[4][2];
            #pragma unroll
            for (int mt = 0; mt < 2; mt++) {
                int mb = m0w + mt * 16 + g;
                af[mt][0] = As[buf][kb + t][mb];
                af[mt][1] = As[buf][kb + t][mb + 8];
                af[mt][2] = As[buf][kb + t + 4][mb];
                af[mt][3] = As[buf][kb + t + 4][mb + 8];
            }
            #pragma unroll
            for (int nt = 0; nt < 4; nt++) {
                int nb = n0w + nt * 8 + g;
                bf[nt][0] = Bs[buf][kb + t][nb];
                bf[nt][1] = Bs[buf][kb + t + 4][nb];
            }
            #pragma unroll
            for (int mt = 0; mt < 2; mt++)
                #pragma unroll
                for (int nt = 0; nt < 4; nt++)
                    mma_tf32(acc[mt][nt][0], acc[mt][nt][1], acc[mt][nt][2], acc[mt][nt][3],
                             af[mt][0], af[mt][1], af[mt][2], af[mt][3],
                             bf[nt][0], bf[nt][1]);
        }

        if (nxt) {
            writeS(buf ^ 1);
            __syncthreads();
            buf ^= 1;
        }
    }

    #pragma unroll
    for (int mt = 0; mt < 2; mt++) {
        int gm = m0 + m0w + mt * 16 + g;
        float bv0 = (EPI >= 1) ? bias[gm] : 0.f;
        float bv8 = (EPI >= 1) ? bias[gm + 8] : 0.f;
        #pragma unroll
        for (int nt = 0; nt < 4; nt++) {
            int gn = n0 + n0w + nt * 8 + 2 * t;
            float v0 = acc[mt][nt][0], v1 = acc[mt][nt][1];
            float v2 = acc[mt][nt][2], v3 = acc[mt][nt][3];
            if (EPI == 1) { v0 += bv0; v1 += bv0; v2 += bv8; v3 += bv8; }
            if (EPI == 2) {
                v0 = tanhf(v0 + bv0); v1 = tanhf(v1 + bv0);
                v2 = tanhf(v2 + bv8); v3 = tanhf(v3 + bv8);
            }
            if (gn < N)     Cp[(size_t)gm * ldc + gn]           = v0;
            if (gn + 1 < N) Cp[(size_t)gm * ldc + gn + 1]       = v1;
            if (gn < N)     Cp[(size_t)(gm + 8) * ldc + gn]     = v2;
            if (gn + 1 < N) Cp[(size_t)(gm + 8) * ldc + gn + 1] = v3;
        }
    }
}

// ============================================================
// gemm_big: scores[p][d] = sum_c q[c][p] * k[c][d], tf32 MMA core.
// CTA 128x128, 256 threads = 8 warps; warp tile 32(m) x 64(n).
// BK=16 (two k8 sub-steps per sync interval).
// ============================================================
__global__ void __launch_bounds__(256) gemm_big_k(
    const float* __restrict__ Aq,   // [C][P] per batch
    const float* __restrict__ Bk,   // [C][D] per batch
    float* __restrict__ Cs)         // [P][D] per batch
{
    __shared__ uint32_t As[2][16][136];
    __shared__ uint32_t Bs[2][16][136];
    const float* Ab = Aq + (size_t)blockIdx.z * C * P;
    const float* Bb = Bk + (size_t)blockIdx.z * C * D;
    float* Cb = Cs + (size_t)blockIdx.z * (size_t)P * D;

    const int m0 = blockIdx.y * 128, n0 = blockIdx.x * 128;
    const int tid = threadIdx.x;
    const int kf = tid >> 5, e4 = (tid & 31) * 4;
    const int warp = tid >> 5, lane = tid & 31;
    const int g = lane >> 2, t = lane & 3;
    const int wm = warp & 3, wn = warp >> 2;
    const int m0w = wm * 32, n0w = wn * 64;

    float acc[2][8][4];
    #pragma unroll
    for (int i = 0; i < 2; i++)
        #pragma unroll
        for (int j = 0; j < 8; j++)
            #pragma unroll
            for (int r = 0; r < 4; r++) acc[i][j][r] = 0.f;

    float4 ra0, ra1, rb0, rb1;
    auto ld4A = [&](int krow, float4& r) {
        const float* src = Ab + (size_t)krow * P;
        int m = m0 + e4;
        if (m + 3 < P) r = *(const float4*)(src + m);
        else {
            r.x = (m+0 < P) ? src[m+0] : 0.f;
            r.y = (m+1 < P) ? src[m+1] : 0.f;
            r.z = (m+2 < P) ? src[m+2] : 0.f;
            r.w = (m+3 < P) ? src[m+3] : 0.f;
        }
    };
    auto ld4B = [&](int krow, float4& r) {
        const float* src = Bb + (size_t)krow * D;
        int n = n0 + e4;
        if (n + 3 < D) r = *(const float4*)(src + n);
        else {
            r.x = (n+0 < D) ? src[n+0] : 0.f;
            r.y = (n+1 < D) ? src[n+1] : 0.f;
            r.z = (n+2 < D) ? src[n+2] : 0.f;
            r.w = (n+3 < D) ? src[n+3] : 0.f;
        }
    };
    auto loadReg = [&](int k0) {
        ld4A(k0 + kf, ra0);
        ld4A(k0 + kf + 8, ra1);
        ld4B(k0 + kf, rb0);
        ld4B(k0 + kf + 8, rb1);
    };
    auto writeS = [&](int buf) {
        As[buf][kf][e4+0] = f2tf32(ra0.x); As[buf][kf][e4+1] = f2tf32(ra0.y);
        As[buf][kf][e4+2] = f2tf32(ra0.z); As[buf][kf][e4+3] = f2tf32(ra0.w);
        As[buf][kf+8][e4+0] = f2tf32(ra1.x); As[buf][kf+8][e4+1] = f2tf32(ra1.y);
        As[buf][kf+8][e4+2] = f2tf32(ra1.z); As[buf][kf+8][e4+3] = f2tf32(ra1.w);
        Bs[buf][kf][e4+0] = f2tf32(rb0.x); Bs[buf][kf][e4+1] = f2tf32(rb0.y);
        Bs[buf][kf][e4+2] = f2tf32(rb0.z); Bs[buf][kf][e4+3] = f2tf32(rb0.w);
        Bs[buf][kf+8][e4+0] = f2tf32(rb1.x); Bs[buf][kf+8][e4+1] = f2tf32(rb1.y);
        Bs[buf][kf+8][e4+2] = f2tf32(rb1.z); Bs[buf][kf+8][e4+3] = f2tf32(rb1.w);
    };

    loadReg(0);
    writeS(0);
    __syncthreads();

    int buf = 0;
    for (int k0 = 0; k0 < C; k0 += 16) {
        bool nxt = (k0 + 16) < C;
        if (nxt) loadReg(k0 + 16);

        #pragma unroll
        for (int ks = 0; ks < 2; ks++) {
            int kb = ks * 8;
            uint32_t af[2][4], bf[8][2];
            #pragma unroll
            for (int mt = 0; mt < 2; mt++) {
                int mb = m0w + mt * 16 + g;
                af[mt][0] = As[buf][kb + t][mb];
                af[mt][1] = As[buf][kb + t][mb + 8];
                af[mt][2] = As[buf][kb + t + 4][mb];
                af[mt][3] = As[buf][kb + t + 4][mb + 8];
            }
            #pragma unroll
            for (int nt = 0; nt < 8; nt++) {
                int nb = n0w + nt * 8 + g;
                bf[nt][0] = Bs[buf][kb + t][nb];
                bf[nt][1] = Bs[buf][kb + t + 4][nb];
            }
            #pragma unroll
            for (int mt = 0; mt < 2; mt++)
                #pragma unroll
                for (int nt = 0; nt < 8; nt++)
                    mma_tf32(acc[mt][nt][0], acc[mt][nt][1], acc[mt][nt][2], acc[mt][nt][3],
                             af[mt][0], af[mt][1], af[mt][2], af[mt][3],
                             bf[nt][0], bf[nt][1]);
        }

        if (nxt) {
            writeS(buf ^ 1);
            __syncthreads();
            buf ^= 1;
        }
    }

    #pragma unroll
    for (int mt = 0; mt < 2; mt++) {
        int gm = m0 + m0w + mt * 16 + g;
        #pragma unroll
        for (int nt = 0; nt < 8; nt++) {
            int gn = n0 + n0w + nt * 8 + 2 * t;
            if (gm < P) {
                if (gn < D)     Cb[(size_t)gm * D + gn]     = acc[mt][nt][0];
                if (gn + 1 < D) Cb[(size_t)gm * D + gn + 1] = acc[mt][nt][1];
            }
            if (gm + 8 < P) {
                if (gn < D)     Cb[(size_t)(gm + 8) * D + gn]     = acc[mt][nt][2];
                if (gn + 1 < D) Cb[(size_t)(gm + 8) * D + gn + 1] = acc[mt][nt][3];
            }
        }
    }
}

// -------- row softmax over D (proven; normalizes in place) --------
__global__ void softmax_k(float* __restrict__ sc)
{
    int n = blockIdx.z, qr = blockIdx.x;
    float* row = sc + ((size_t)n * P + qr) * D;
    __shared__ float red[256];
    int tid = threadIdx.x;
    float m = -1e30f;
    for (int d = tid; d < D; d += 256) m = fmaxf(m, row[d]);
    red[tid] = m; __syncthreads();
    for (int s = 128; s > 0; s >>= 1) { if (tid < s) red[tid] = fmaxf(red[tid], red[tid + s]); __syncthreads(); }
    m = red[0]; __syncthreads();
    float sum = 0.f;
    for (int d = tid; d < D; d += 256) { float e = __expf(row[d] - m); row[d] = e; sum += e; }
    red[tid] = sum; __syncthreads();
    for (int s = 128; s > 0; s >>= 1) { if (tid < s) red[tid] += red[tid + s]; __syncthreads(); }
    float inv = 1.0f / red[0];
    for (int d = tid; d < D; d += 256) row[d] *= inv;
}

// -------- beff = b_h + W_h[:,2C:3C] @ v_c; v_c from constant c0 --------
__global__ void beff_k(const float* __restrict__ w_vc, const float* __restrict__ c0,
                       const float* __restrict__ w_h, const float* __restrict__ b_h,
                       float* __restrict__ beff)
{
    __shared__ float vc[C];
    int c = threadIdx.x;  // 128 threads
    float s = 0.f;
    for (int ci = 0; ci < C; ci++) {
        float ws = 0.f;
        #pragma unroll
        for (int t = 0; t < 9; t++) ws += w_vc[((size_t)c * C + ci) * 9 + t];
        s += ws * c0[ci];
    }
    vc[c] = s;
    __syncthreads();
    float r = b_h[c];
    for (int j = 0; j < C; j++) r += w_h[(size_t)c * (3*C) + 2*C + j] * vc[j];
    beff[c] = r;
}

extern "C" void kernel_launch(void* const* d_in, const int* in_sizes, int n_in,
                              void* d_out, int out_size)
{
    const float* inp  = (const float*)d_in[0];
    const float* c0   = (const float*)d_in[1];
    const float* w_x  = (const float*)d_in[2];
    const float* b_x  = (const float*)d_in[3];
    const float* w_qx = (const float*)d_in[4];
    const float* w_kx = (const float*)d_in[6];
    const float* w_vx = (const float*)d_in[8];
    const float* w_vc = (const float*)d_in[9];
    const float* w_h  = (const float*)d_in[14];
    const float* b_h  = (const float*)d_in[15];
    const float* w_o  = (const float*)d_in[16];
    const float* b_o  = (const float*)d_in[17];
    float* out = (float*)d_out;

    float *xa, *q, *k, *v, *sc, *h, *beff;
    cudaGetSymbolAddress((void**)&xa,   g_xa);
    cudaGetSymbolAddress((void**)&q,    g_q);
    cudaGetSymbolAddress((void**)&k,    g_k);
    cudaGetSymbolAddress((void**)&v,    g_v);
    cudaGetSymbolAddress((void**)&sc,   g_sc);
    cudaGetSymbolAddress((void**)&h,    g_h);
    cudaGetSymbolAddress((void**)&beff, g_beff);

    const int NT_P = (P + 63) / 64;   // 21

    // folded constant bias for proj_h (v_c branch)
    beff_k<<<1, C>>>(w_vc, c0, w_h, b_h, beff);

    // x = W_x @ inp + b_x  (tf32 MMA) -> g_xa rows [0,128)
    gemm64t_k<0,1><<<dim3(NT_P, 2, NB), 128>>>(
        w_x, 0, C, inp, (size_t)C*P, P, xa, (size_t)2*C*P, P, P, C, b_x);

    // q/k/v 3x3 convs, tf32 MMA mega-launch (22 q-tiles + 40 kv-tiles per batch)
    qkv_mega_k<<<dim3(62, 1, NB), 128>>>(xa, w_qx, w_kx, w_vx, q, k, v);

    // scores[p,d] = q^T k  (tf32 MMA, BK=16)
    gemm_big_k<<<dim3((D + 127)/128, (P + 127)/128, NB), 256>>>(q, k, sc);

    // softmax rows (normalize in place)
    softmax_k<<<dim3(P, 1, NB), 256>>>(sc);

    // a0[c,p] = v @ probs^T  (tf32 MMA) -> g_xa rows [128,256)
    gemm64t_k<1,0><<<dim3(NT_P, 2, NB), 128>>>(
        v, (size_t)C*D, D, sc, (size_t)P*D, D, xa + (size_t)C*P, (size_t)2*C*P, P, P, D, b_x);

    // h = tanh(W_h[:, :2C] @ [x; a0] + beff)  (tf32 MMA)
    gemm64t_k<0,2><<<dim3(NT_P, 2, NB), 128>>>(
        w_h, 0, 3*C, xa, (size_t)2*C*P, P, h, (size_t)C*P, P, P, 2*C, beff);

    // out = W_o @ h + b_o  (tf32 MMA)
    gemm64t_k<0,1><<<dim3(NT_P, 2, NB), 128>>>(
        w_o, 0, C, h, (size_t)C*P, P, out, (size_t)C*P, P, P, C, b_o);
}

// round 11
// speedup vs baseline: 2.9515x; 1.0878x over previous
#include <cuda_runtime.h>
#include <cstdint>
#include <cstddef>

// Problem dims
#define NB 8
#define C 128
#define HH 36
#define WW 36
#define P (HH*WW)          // 1296 query tokens
#define HV 34
#define WV 34
#define D (HV*WV)          // 1156 key/value tokens
#define KC (C*9)           // 1152 im2col K

// -------- scratch (static device memory; no allocation APIs) --------
// Intermediates stored as tf32 bit patterns (uint32_t).
__device__ uint32_t g_xa[(size_t)NB*2*C*P];   // rows 0..127: x, rows 128..255: a0
__device__ uint32_t g_q[(size_t)NB*C*P];
__device__ uint32_t g_k[(size_t)NB*C*D];
__device__ uint32_t g_v[(size_t)NB*C*D];
__device__ uint32_t g_sc[(size_t)NB*(size_t)P*D]; // exp(scores) tf32 bits
__device__ float    g_rs[(size_t)NB*P];           // row sums of exp
__device__ uint32_t g_h[(size_t)NB*C*P];
__device__ float    g_beff[C];
// pre-converted tf32 weights
__device__ uint32_t g_wx[C*C];
__device__ uint32_t g_wq[C*KC];
__device__ uint32_t g_wk[C*KC];
__device__ uint32_t g_wv[C*KC];
__device__ uint32_t g_wh[C*3*C];
__device__ uint32_t g_wo[C*C];

// -------- tf32 helpers --------
__device__ __forceinline__ uint32_t f2tf32(float f) {
    uint32_t u;
    asm("cvt.rna.tf32.f32 %0, %1;" : "=r"(u) : "f"(f));
    return u;
}

__device__ __forceinline__ void mma_tf32(
    float& c0, float& c1, float& c2, float& c3,
    uint32_t a0, uint32_t a1, uint32_t a2, uint32_t a3,
    uint32_t b0, uint32_t b1)
{
    asm volatile(
        "mma.sync.aligned.m16n8k8.row.col.f32.tf32.tf32.f32 "
        "{%0,%1,%2,%3}, {%4,%5,%6,%7}, {%8,%9}, {%0,%1,%2,%3};"
        : "+f"(c0), "+f"(c1), "+f"(c2), "+f"(c3)
        : "r"(a0), "r"(a1), "r"(a2), "r"(a3), "r"(b0), "r"(b1));
}

// -------- weight pre-conversion (fp32 -> tf32 bits), one pass --------
__global__ void preconv_k(const float* __restrict__ wx, const float* __restrict__ wq,
                          const float* __restrict__ wk, const float* __restrict__ wv,
                          const float* __restrict__ wh, const float* __restrict__ wo)
{
    int i = blockIdx.x * 256 + threadIdx.x;
    if (i < C*C)   { g_wx[i] = f2tf32(wx[i]); g_wo[i] = f2tf32(wo[i]); }
    if (i < C*3*C) g_wh[i] = f2tf32(wh[i]);
    if (i < C*KC)  {
        g_wq[i] = f2tf32(wq[i]);
        g_wk[i] = f2tf32(wk[i]);
        g_wv[i] = f2tf32(wv[i]);
    }
}

__global__ void zero_rs_k()
{
    int i = blockIdx.x * 256 + threadIdx.x;
    if (i < NB * P) g_rs[i] = 0.f;
}

// ============================================================
// qkv_mega: all three 3x3 conv GEMMs in ONE launch, tf32 MMA core.
// CTA tile 64(m) x 128(n), 128 threads = 4 warps, warp tile 32x64.
// A = pre-converted tf32 weights; B gathered raw from tf32 x.
// ============================================================
__global__ void __launch_bounds__(128) qkv_mega_k(
    const uint32_t* __restrict__ xa,
    uint32_t* __restrict__ qo, uint32_t* __restrict__ ko, uint32_t* __restrict__ vo)
{
    __shared__ uint32_t As[2][16][72];
    __shared__ uint32_t Bs[2][16][136];

    const int bz = blockIdx.z;
    const int tile = blockIdx.x;
    bool qmode; int my, nx;
    if (tile < 22) { qmode = true;  my = tile / 11; nx = tile % 11; }
    else { int t2 = tile - 22; qmode = false; my = t2 / 10; nx = t2 % 10; }

    const uint32_t* A = qmode ? g_wq : ((my < 2) ? g_wk : g_wv);
    const int m0 = qmode ? my * 64 : (my & 1) * 64;
    const int Nn = qmode ? P : D;
    uint32_t* Cp = qmode ? (qo + (size_t)bz * C * P)
                         : ((my < 2) ? ko : vo) + (size_t)bz * C * D;
    const uint32_t* B = xa + (size_t)bz * 2 * C * P;   // x rows [0,128)
    const int n0 = nx * 128;
    const int ldc = Nn;

    const int tid = threadIdx.x;
    const int warp = tid >> 5, lane = tid & 31;
    const int g = lane >> 2, t = lane & 3;
    const int wm = warp & 1, wn = warp >> 1;
    const int m0w = wm * 32, n0w = wn * 64;

    const int ka = tid & 15;        // A slot: k fixed, m = (tid>>4)+8i
    const int ma = tid >> 4;

    int p = n0 + tid;
    bool npred; int iy, ix;
    if (qmode) { npred = (p < P); if (p >= P) p = 0; iy = p / WW; ix = p % WW; }
    else       { npred = (p < D); if (p >= D) p = 0; iy = p / WV; ix = p % WV; }

    float acc[2][8][4];
    #pragma unroll
    for (int i = 0; i < 2; i++)
        #pragma unroll
        for (int j = 0; j < 8; j++)
            #pragma unroll
            for (int r = 0; r < 4; r++) acc[i][j][r] = 0.f;

    uint32_t ra[8], rb[16];

    auto loadAB = [&](int k0) {
        int ci_a = (k0 + ka) & 127, t_a = (k0 + ka) >> 7;
        #pragma unroll
        for (int i = 0; i < 8; i++) {
            int m = m0 + ma + 8 * i;
            ra[i] = A[(size_t)m * KC + ci_a * 9 + t_a];
        }
        int tt = k0 >> 7;
        int ky = tt / 3, kx = tt - ky * 3;
        int cb = k0 & 127;
        if (qmode) {
            int sy = iy + ky - 1, sx = ix + kx - 1;
            bool pr = npred && sy >= 0 && sy < HH && sx >= 0 && sx < WW;
            int rowb = sy * WW + sx;
            #pragma unroll
            for (int i = 0; i < 16; i++)
                rb[i] = pr ? B[(size_t)(cb + i) * P + rowb] : 0u;
        } else {
            int rowb = (iy + ky) * WW + (ix + kx);
            #pragma unroll
            for (int i = 0; i < 16; i++)
                rb[i] = npred ? B[(size_t)(cb + i) * P + rowb] : 0u;
        }
    };

    auto writeS = [&](int buf) {
        #pragma unroll
        for (int i = 0; i < 8; i++) As[buf][ka][ma + 8 * i] = ra[i];
        #pragma unroll
        for (int i = 0; i < 16; i++) Bs[buf][i][tid] = rb[i];
    };

    loadAB(0);
    writeS(0);
    __syncthreads();

    int buf = 0;
    for (int k0 = 0; k0 < KC; k0 += 16) {
        bool nxt = (k0 + 16) < KC;
        if (nxt) loadAB(k0 + 16);

        #pragma unroll
        for (int ks = 0; ks < 2; ks++) {
            int kb = ks * 8;
            uint32_t af[2][4], bf[8][2];
            #pragma unroll
            for (int mt = 0; mt < 2; mt++) {
                int mb = m0w + mt * 16 + g;
                af[mt][0] = As[buf][kb + t][mb];
                af[mt][1] = As[buf][kb + t][mb + 8];
                af[mt][2] = As[buf][kb + t + 4][mb];
                af[mt][3] = As[buf][kb + t + 4][mb + 8];
            }
            #pragma unroll
            for (int nt = 0; nt < 8; nt++) {
                int nb = n0w + nt * 8 + g;
                bf[nt][0] = Bs[buf][kb + t][nb];
                bf[nt][1] = Bs[buf][kb + t + 4][nb];
            }
            #pragma unroll
            for (int mt = 0; mt < 2; mt++)
                #pragma unroll
                for (int nt = 0; nt < 8; nt++)
                    mma_tf32(acc[mt][nt][0], acc[mt][nt][1], acc[mt][nt][2], acc[mt][nt][3],
                             af[mt][0], af[mt][1], af[mt][2], af[mt][3],
                             bf[nt][0], bf[nt][1]);
        }

        if (nxt) {
            writeS(buf ^ 1);
            __syncthreads();
            buf ^= 1;
        }
    }

    #pragma unroll
    for (int mt = 0; mt < 2; mt++) {
        int gm = m0 + m0w + mt * 16 + g;
        #pragma unroll
        for (int nt = 0; nt < 8; nt++) {
            int gn = n0 + n0w + nt * 8 + 2 * t;
            if (gn < Nn)     Cp[(size_t)gm * ldc + gn]           = f2tf32(acc[mt][nt][0]);
            if (gn + 1 < Nn) Cp[(size_t)gm * ldc + gn + 1]       = f2tf32(acc[mt][nt][1]);
            if (gn < Nn)     Cp[(size_t)(gm + 8) * ldc + gn]     = f2tf32(acc[mt][nt][2]);
            if (gn + 1 < Nn) Cp[(size_t)(gm + 8) * ldc + gn + 1] = f2tf32(acc[mt][nt][3]);
        }
    }
}

// ============================================================
// gemm64t: tf32 MMA 64x64 GEMM. C[128,N] = A[128,K] @ B[K,N].
// A is always pre-converted tf32 bits (u32).
// BMODE: 0 = B plain [K][N], 1 = B transposed [N][K].
// BRAW:  true = B already tf32 bits, false = B fp32 (cvt at load).
// EPI: 0 none, 1 +bias[m], 2 tanh(acc+bias[m]), 3 column scale 1/aux[n]
// OU32: write tf32 bits (true) or fp32 (false).
// ============================================================
template<int BMODE, int EPI, bool BRAW, bool OU32>
__global__ void __launch_bounds__(128) gemm64t_k(
    const uint32_t* __restrict__ A, size_t sA, int lda,
    const void* __restrict__ Bv, size_t sB, int ldb,
    void* __restrict__ Cv, size_t sC, int ldc,
    int N, int K,
    const float* __restrict__ aux, size_t sAux)
{
    __shared__ uint32_t As[2][16][72];
    __shared__ uint32_t Bs[2][16][72];
    A += (size_t)blockIdx.z * sA;
    const uint32_t* B32 = (const uint32_t*)Bv + (BRAW ? (size_t)blockIdx.z * sB : 0);
    const float*    Bf  = (const float*)Bv    + (BRAW ? 0 : (size_t)blockIdx.z * sB);
    uint32_t* C32 = (uint32_t*)Cv + (size_t)blockIdx.z * sC;
    float*    Cf  = (float*)Cv    + (size_t)blockIdx.z * sC;
    const float* auxp = aux + (size_t)blockIdx.z * sAux;

    const int m0 = blockIdx.y * 64, n0 = blockIdx.x * 64;
    const int tid = threadIdx.x;
    const int warp = tid >> 5, lane = tid & 31;
    const int g = lane >> 2, t = lane & 3;
    const int wm = warp & 1, wn = warp >> 1;
    const int m0w = wm * 32, n0w = wn * 32;

    const int ka = tid & 15;
    const int ma = tid >> 4;
    const int nb64 = tid & 63;
    const int kb2 = tid >> 6;
    const int kb16 = tid & 15;

    float acc[2][4][4];
    #pragma unroll
    for (int i = 0; i < 2; i++)
        #pragma unroll
        for (int j = 0; j < 4; j++)
            #pragma unroll
            for (int r = 0; r < 4; r++) acc[i][j][r] = 0.f;

    uint32_t ra[8], rb[8];

    auto ldB = [&](int gk, int gn) -> uint32_t {
        if (gn >= N || gk >= K) return 0u;
        if (BRAW) return B32[(size_t)(BMODE == 1 ? gn : gk) * ldb + (BMODE == 1 ? gk : gn)];
        else      return f2tf32(Bf[(size_t)(BMODE == 1 ? gn : gk) * ldb + (BMODE == 1 ? gk : gn)]);
    };

    auto loadAB = [&](int k0) {
        #pragma unroll
        for (int i = 0; i < 8; i++) {
            int gk = k0 + ka;
            int m = m0 + ma + 8 * i;
            ra[i] = (gk < K) ? A[(size_t)m * lda + gk] : 0u;
        }
        if (BMODE == 0) {
            #pragma unroll
            for (int i = 0; i < 8; i++)
                rb[i] = ldB(k0 + kb2 + 2 * i, n0 + nb64);
        } else {
            #pragma unroll
            for (int i = 0; i < 8; i++)
                rb[i] = ldB(k0 + kb16, n0 + (tid >> 4) + 8 * i);
        }
    };

    auto writeS = [&](int buf) {
        #pragma unroll
        for (int i = 0; i < 8; i++) As[buf][ka][ma + 8 * i] = ra[i];
        if (BMODE == 1) {
            #pragma unroll
            for (int i = 0; i < 8; i++) Bs[buf][kb16][(tid >> 4) + 8 * i] = rb[i];
        } else {
            #pragma unroll
            for (int i = 0; i < 8; i++) Bs[buf][kb2 + 2 * i][nb64] = rb[i];
        }
    };

    loadAB(0);
    writeS(0);
    __syncthreads();

    int buf = 0;
    for (int k0 = 0; k0 < K; k0 += 16) {
        bool nxt = (k0 + 16) < K;
        if (nxt) loadAB(k0 + 16);

        #pragma unroll
        for (int ks = 0; ks < 2; ks++) {
            int kb = ks * 8;
            uint32_t af[2][4], bf[4][2];
            #pragma unroll
            for (int mt = 0; mt < 2; mt++) {
                int mb = m0w + mt * 16 + g;
                af[mt][0] = As[buf][kb + t][mb];
                af[mt][1] = As[buf][kb + t][mb + 8];
                af[mt][2] = As[buf][kb + t + 4][mb];
                af[mt][3] = As[buf][kb + t + 4][mb + 8];
            }
            #pragma unroll
            for (int nt = 0; nt < 4; nt++) {
                int nb = n0w + nt * 8 + g;
                bf[nt][0] = Bs[buf][kb + t][nb];
                bf[nt][1] = Bs[buf][kb + t + 4][nb];
            }
            #pragma unroll
            for (int mt = 0; mt < 2; mt++)
                #pragma unroll
                for (int nt = 0; nt < 4; nt++)
                    mma_tf32(acc[mt][nt][0], acc[mt][nt][1], acc[mt][nt][2], acc[mt][nt][3],
                             af[mt][0], af[mt][1], af[mt][2], af[mt][3],
                             bf[nt][0], bf[nt][1]);
        }

        if (nxt) {
            writeS(buf ^ 1);
            __syncthreads();
            buf ^= 1;
        }
    }

    #pragma unroll
    for (int mt = 0; mt < 2; mt++) {
        int gm = m0 + m0w + mt * 16 + g;
        float bv0 = (EPI == 1 || EPI == 2) ? auxp[gm] : 0.f;
        float bv8 = (EPI == 1 || EPI == 2) ? auxp[gm + 8] : 0.f;
        #pragma unroll
        for (int nt = 0; nt < 4; nt++) {
            int gn = n0 + n0w + nt * 8 + 2 * t;
            float v0 = acc[mt][nt][0], v1 = acc[mt][nt][1];
            float v2 = acc[mt][nt][2], v3 = acc[mt][nt][3];
            if (EPI == 1) { v0 += bv0; v1 += bv0; v2 += bv8; v3 += bv8; }
            if (EPI == 2) {
                v0 = tanhf(v0 + bv0); v1 = tanhf(v1 + bv0);
                v2 = tanhf(v2 + bv8); v3 = tanhf(v3 + bv8);
            }
            if (EPI == 3) {
                float i0 = (gn < N)     ? 1.f / auxp[gn]     : 0.f;
                float i1 = (gn + 1 < N) ? 1.f / auxp[gn + 1] : 0.f;
                v0 *= i0; v1 *= i1; v2 *= i0; v3 *= i1;
            }
            if (OU32) {
                if (gn < N)     C32[(size_t)gm * ldc + gn]           = f2tf32(v0);
                if (gn + 1 < N) C32[(size_t)gm * ldc + gn + 1]       = f2tf32(v1);
                if (gn < N)     C32[(size_t)(gm + 8) * ldc + gn]     = f2tf32(v2);
                if (gn + 1 < N) C32[(size_t)(gm + 8) * ldc + gn + 1] = f2tf32(v3);
            } else {
                if (gn < N)     Cf[(size_t)gm * ldc + gn]           = v0;
                if (gn + 1 < N) Cf[(size_t)gm * ldc + gn + 1]       = v1;
                if (gn < N)     Cf[(size_t)(gm + 8) * ldc + gn]     = v2;
                if (gn + 1 < N) Cf[(size_t)(gm + 8) * ldc + gn + 1] = v3;
            }
        }
    }
}

// ============================================================
// gemm_big: exp-scores. ex[p][d] = exp(sum_c q[c][p]*k[c][d]),
// row sums accumulated into g_rs via atomics. tf32 MMA, BK=16.
// CTA 128x128, 256 threads = 8 warps; warp tile 32(m) x 64(n).
// ============================================================
__global__ void __launch_bounds__(256) gemm_big_k(
    const uint32_t* __restrict__ Aq,   // [C][P] per batch, tf32 bits
    const uint32_t* __restrict__ Bk,   // [C][D] per batch, tf32 bits
    uint32_t* __restrict__ Cs,         // [P][D] per batch, exp tf32 bits
    float* __restrict__ rs)            // [P] per batch
{
    __shared__ uint32_t As[2][16][136];
    __shared__ uint32_t Bs[2][16][136];
    const uint32_t* Ab = Aq + (size_t)blockIdx.z * C * P;
    const uint32_t* Bb = Bk + (size_t)blockIdx.z * C * D;
    uint32_t* Cb = Cs + (size_t)blockIdx.z * (size_t)P * D;
    float* rsb = rs + (size_t)blockIdx.z * P;

    const int m0 = blockIdx.y * 128, n0 = blockIdx.x * 128;
    const int tid = threadIdx.x;
    const int kf = tid >> 5, e4 = (tid & 31) * 4;
    const int warp = tid >> 5, lane = tid & 31;
    const int g = lane >> 2, t = lane & 3;
    const int wm = warp & 3, wn = warp >> 2;
    const int m0w = wm * 32, n0w = wn * 64;

    float acc[2][8][4];
    #pragma unroll
    for (int i = 0; i < 2; i++)
        #pragma unroll
        for (int j = 0; j < 8; j++)
            #pragma unroll
            for (int r = 0; r < 4; r++) acc[i][j][r] = 0.f;

    uint4 ra0, ra1, rb0, rb1;
    auto ld4A = [&](int krow, uint4& r) {
        const uint32_t* src = Ab + (size_t)krow * P;
        int m = m0 + e4;
        if (m + 3 < P) r = *(const uint4*)(src + m);
        else {
            r.x = (m+0 < P) ? src[m+0] : 0u;
            r.y = (m+1 < P) ? src[m+1] : 0u;
            r.z = (m+2 < P) ? src[m+2] : 0u;
            r.w = (m+3 < P) ? src[m+3] : 0u;
        }
    };
    auto ld4B = [&](int krow, uint4& r) {
        const uint32_t* src = Bb + (size_t)krow * D;
        int n = n0 + e4;
        if (n + 3 < D) r = *(const uint4*)(src + n);
        else {
            r.x = (n+0 < D) ? src[n+0] : 0u;
            r.y = (n+1 < D) ? src[n+1] : 0u;
            r.z = (n+2 < D) ? src[n+2] : 0u;
            r.w = (n+3 < D) ? src[n+3] : 0u;
        }
    };
    auto loadReg = [&](int k0) {
        ld4A(k0 + kf, ra0);
        ld4A(k0 + kf + 8, ra1);
        ld4B(k0 + kf, rb0);
        ld4B(k0 + kf + 8, rb1);
    };
    auto writeS = [&](int buf) {
        *(uint4*)&As[buf][kf][e4]   = ra0;
        *(uint4*)&As[buf][kf+8][e4] = ra1;
        *(uint4*)&Bs[buf][kf][e4]   = rb0;
        *(uint4*)&Bs[buf][kf+8][e4] = rb1;
    };

    loadReg(0);
    writeS(0);
    __syncthreads();

    int buf = 0;
    for (int k0 = 0; k0 < C; k0 += 16) {
        bool nxt = (k0 + 16) < C;
        if (nxt) loadReg(k0 + 16);

        #pragma unroll
        for (int ks = 0; ks < 2; ks++) {
            int kb = ks * 8;
            uint32_t af[2][4], bf[8][2];
            #pragma unroll
            for (int mt = 0; mt < 2; mt++) {
                int mb = m0w + mt * 16 + g;
                af[mt][0] = As[buf][kb + t][mb];
                af[mt][1] = As[buf][kb + t][mb + 8];
                af[mt][2] = As[buf][kb + t + 4][mb];
                af[mt][3] = As[buf][kb + t + 4][mb + 8];
            }
            #pragma unroll
            for (int nt = 0; nt < 8; nt++) {
                int nb = n0w + nt * 8 + g;
                bf[nt][0] = Bs[buf][kb + t][nb];
                bf[nt][1] = Bs[buf][kb + t + 4][nb];
            }
            #pragma unroll
            for (int mt = 0; mt < 2; mt++)
                #pragma unroll
                for (int nt = 0; nt < 8; nt++)
                    mma_tf32(acc[mt][nt][0], acc[mt][nt][1], acc[mt][nt][2], acc[mt][nt][3],
                             af[mt][0], af[mt][1], af[mt][2], af[mt][3],
                             bf[nt][0], bf[nt][1]);
        }

        if (nxt) {
            writeS(buf ^ 1);
            __syncthreads();
            buf ^= 1;
        }
    }

    // epilogue: exp, store tf32 bits, accumulate row sums
    #pragma unroll
    for (int mt = 0; mt < 2; mt++) {
        int gm = m0 + m0w + mt * 16 + g;
        float s0 = 0.f, s1 = 0.f;
        #pragma unroll
        for (int nt = 0; nt < 8; nt++) {
            int gn = n0 + n0w + nt * 8 + 2 * t;
            bool c0 = (gn < D), c1 = (gn + 1 < D);
            float e0 = __expf(acc[mt][nt][0]);
            float e1 = __expf(acc[mt][nt][1]);
            float e2 = __expf(acc[mt][nt][2]);
            float e3 = __expf(acc[mt][nt][3]);
            if (gm < P) {
                if (c0) Cb[(size_t)gm * D + gn]     = f2tf32(e0);
                if (c1) Cb[(size_t)gm * D + gn + 1] = f2tf32(e1);
            }
            if (gm + 8 < P) {
                if (c0) Cb[(size_t)(gm + 8) * D + gn]     = f2tf32(e2);
                if (c1) Cb[(size_t)(gm + 8) * D + gn + 1] = f2tf32(e3);
            }
            s0 += (c0 ? e0 : 0.f) + (c1 ? e1 : 0.f);
            s1 += (c0 ? e2 : 0.f) + (c1 ? e3 : 0.f);
        }
        // reduce over the 4 lanes sharing row gm (lanes differ in t = low 2 bits)
        s0 += __shfl_xor_sync(0xffffffff, s0, 1);
        s0 += __shfl_xor_sync(0xffffffff, s0, 2);
        s1 += __shfl_xor_sync(0xffffffff, s1, 1);
        s1 += __shfl_xor_sync(0xffffffff, s1, 2);
        if (t == 0) {
            if (gm < P)     atomicAdd(&rsb[gm], s0);
            if (gm + 8 < P) atomicAdd(&rsb[gm + 8], s1);
        }
    }
}

// -------- beff = b_h + W_h[:,2C:3C] @ v_c; v_c from constant c0 --------
__global__ void beff_k(const float* __restrict__ w_vc, const float* __restrict__ c0,
                       const float* __restrict__ w_h, const float* __restrict__ b_h,
                       float* __restrict__ beff)
{
    __shared__ float vc[C];
    int c = threadIdx.x;  // 128 threads
    float s = 0.f;
    for (int ci = 0; ci < C; ci++) {
        float ws = 0.f;
        #pragma unroll
        for (int t = 0; t < 9; t++) ws += w_vc[((size_t)c * C + ci) * 9 + t];
        s += ws * c0[ci];
    }
    vc[c] = s;
    __syncthreads();
    float r = b_h[c];
    for (int j = 0; j < C; j++) r += w_h[(size_t)c * (3*C) + 2*C + j] * vc[j];
    beff[c] = r;
}

extern "C" void kernel_launch(void* const* d_in, const int* in_sizes, int n_in,
                              void* d_out, int out_size)
{
    const float* inp  = (const float*)d_in[0];
    const float* c0   = (const float*)d_in[1];
    const float* w_x  = (const float*)d_in[2];
    const float* b_x  = (const float*)d_in[3];
    const float* w_qx = (const float*)d_in[4];
    const float* w_kx = (const float*)d_in[6];
    const float* w_vx = (const float*)d_in[8];
    const float* w_vc = (const float*)d_in[9];
    const float* w_h  = (const float*)d_in[14];
    const float* b_h  = (const float*)d_in[15];
    const float* w_o  = (const float*)d_in[16];
    const float* b_o  = (const float*)d_in[17];
    float* out = (float*)d_out;

    uint32_t *xa, *q, *k, *v, *sc, *h;
    float *rs, *beff;
    cudaGetSymbolAddress((void**)&xa,   g_xa);
    cudaGetSymbolAddress((void**)&q,    g_q);
    cudaGetSymbolAddress((void**)&k,    g_k);
    cudaGetSymbolAddress((void**)&v,    g_v);
    cudaGetSymbolAddress((void**)&sc,   g_sc);
    cudaGetSymbolAddress((void**)&rs,   g_rs);
    cudaGetSymbolAddress((void**)&h,    g_h);
    cudaGetSymbolAddress((void**)&beff, g_beff);
    uint32_t *wx;
    cudaGetSymbolAddress((void**)&wx, g_wx);
    uint32_t *wh, *wo;
    cudaGetSymbolAddress((void**)&wh, g_wh);
    cudaGetSymbolAddress((void**)&wo, g_wo);

    const int NT_P = (P + 63) / 64;   // 21

    // constants and weight pre-conversion
    beff_k<<<1, C>>>(w_vc, c0, w_h, b_h, beff);
    preconv_k<<<(C*KC + 255)/256, 256>>>(w_x, w_qx, w_kx, w_vx, w_h, w_o);
    zero_rs_k<<<(NB*P + 255)/256, 256>>>();

    // x = W_x @ inp + b_x -> g_xa rows [0,128) as tf32 bits
    gemm64t_k<0,1,false,true><<<dim3(NT_P, 2, NB), 128>>>(
        wx, 0, C, inp, (size_t)C*P, P, xa, (size_t)2*C*P, P, P, C, b_x, 0);

    // q/k/v 3x3 convs, tf32 MMA mega-launch
    qkv_mega_k<<<dim3(62, 1, NB), 128>>>(xa, q, k, v);

    // ex[p,d] = exp(q^T k) + row sums (fused)
    gemm_big_k<<<dim3((D + 127)/128, (P + 127)/128, NB), 256>>>(q, k, sc, rs);

    // a0[c,p] = (v @ ex^T)[c,p] / rs[p] -> g_xa rows [128,256)
    gemm64t_k<1,3,true,true><<<dim3(NT_P, 2, NB), 128>>>(
        v, (size_t)C*D, D, sc, (size_t)P*D, D, xa + (size_t)C*P, (size_t)2*C*P, P,
        P, D, rs, P);

    // h = tanh(W_h[:, :2C] @ [x; a0] + beff)
    gemm64t_k<0,2,true,true><<<dim3(NT_P, 2, NB), 128>>>(
        wh, 0, 3*C, xa, (size_t)2*C*P, P, h, (size_t)C*P, P, P, 2*C, beff, 0);

    // out = W_o @ h + b_o  (fp32 output)
    gemm64t_k<0,1,true,false><<<dim3(NT_P, 2, NB), 128>>>(
        wo, 0, C, h, (size_t)C*P, P, out, (size_t)C*P, P, P, C, b_o, 0);
}